// round 2
// baseline (speedup 1.0000x reference)
#include <cuda_runtime.h>
#include <cstdint>
#include <cstddef>

// Problem constants
#define BB   8
#define TT   1024
#define DD   512
#define EE   1024      // 2*D projection width
#define NTAPE 64
#define CPB  16        // CTAs per batch (= cluster size)
#define RPC  32        // rows (and tape cols) per CTA = D / CPB
#define NTHREADS 256

// ---------------- device scratch (static: no allocations allowed) ----------
__device__ float    g_xz[(size_t)BB * TT * EE];     // projected x || z  (33.5 MB)
__device__ float    g_rs[BB * CPB * NTAPE];         // read-score partials (fallback)
__device__ float    g_ws[BB * CPB * NTAPE];         // write-score partials (fallback)
__device__ float    g_hnew[BB * DD];                // h_new exchange (fallback)
__device__ unsigned g_bar[BB];                      // per-batch barrier counters (fallback)

__global__ void init_bar_kernel() {
    if (threadIdx.x < BB) g_bar[threadIdx.x] = 0u;
}

// ---------------- projection GEMM: g_xz[m][e] = sum_k X[m][k]*Wxz[e][k] ----
__global__ __launch_bounds__(256) void gemm_xz_kernel(
    const float* __restrict__ X, const float* __restrict__ W)
{
    __shared__ float As[16][68];
    __shared__ float Bs[16][68];

    const int m0 = blockIdx.y * 64;
    const int e0 = blockIdx.x * 64;
    const int tid = threadIdx.x;
    const int tx = tid & 15;
    const int ty = tid >> 4;
    const int lr = tid >> 2;
    const int lc = (tid & 3) * 4;

    float acc[4][4] = {};

    for (int kt = 0; kt < 512; kt += 16) {
        float4 xv = *(const float4*)(X + (size_t)(m0 + lr) * 512 + kt + lc);
        float4 wv = *(const float4*)(W + (size_t)(e0 + lr) * 512 + kt + lc);
        __syncthreads();
        As[lc + 0][lr] = xv.x; As[lc + 1][lr] = xv.y;
        As[lc + 2][lr] = xv.z; As[lc + 3][lr] = xv.w;
        Bs[lc + 0][lr] = wv.x; Bs[lc + 1][lr] = wv.y;
        Bs[lc + 2][lr] = wv.z; Bs[lc + 3][lr] = wv.w;
        __syncthreads();
#pragma unroll
        for (int kk = 0; kk < 16; kk++) {
            float4 a  = *(const float4*)&As[kk][ty * 4];
            float4 bv = *(const float4*)&Bs[kk][tx * 4];
            float av[4] = {a.x, a.y, a.z, a.w};
            float bw[4] = {bv.x, bv.y, bv.z, bv.w};
#pragma unroll
            for (int i = 0; i < 4; i++)
#pragma unroll
                for (int j = 0; j < 4; j++)
                    acc[i][j] += av[i] * bw[j];
        }
    }
#pragma unroll
    for (int i = 0; i < 4; i++) {
        float4 o = make_float4(acc[i][0], acc[i][1], acc[i][2], acc[i][3]);
        *(float4*)(&g_xz[(size_t)(m0 + ty * 4 + i) * EE + e0 + tx * 4]) = o;
    }
}

// ---------------- shared helpers ------------------------------------------
__device__ __forceinline__ uint32_t smem_u32(const void* p) {
    return (uint32_t)__cvta_generic_to_shared(p);
}
__device__ __forceinline__ uint32_t mapa_u32(uint32_t local_addr, uint32_t rank) {
    uint32_t r;
    asm volatile("mapa.shared::cluster.u32 %0, %1, %2;"
                 : "=r"(r) : "r"(local_addr), "r"(rank));
    return r;
}
__device__ __forceinline__ void st_cluster_f32(uint32_t addr, float v) {
    asm volatile("st.shared::cluster.f32 [%0], %1;" :: "r"(addr), "f"(v) : "memory");
}
#define CLUSTER_SYNC_() do {                                              \
    asm volatile("barrier.cluster.arrive.aligned;" ::: "memory");         \
    asm volatile("barrier.cluster.wait.aligned;"   ::: "memory");         \
} while (0)

__device__ __forceinline__ unsigned ld_acq_u32(const unsigned* p) {
    unsigned v;
    asm volatile("ld.global.acquire.gpu.u32 %0, [%1];" : "=r"(v) : "l"(p));
    return v;
}
__device__ __forceinline__ void batch_barrier(int b, unsigned target) {
    __syncthreads();
    if (threadIdx.x == 0) {
        __threadfence();
        atomicAdd(&g_bar[b], 1u);
        while (ld_acq_u32(&g_bar[b]) < target) { }
    }
    __syncthreads();
}

// Conflict-free matvec: dest[r] = sum_j sW[r*512+j]*vec[j], r = 0..31.
// Each lane loads contiguous float4 at lane*16B (canonical LDS.128 pattern),
// chunks strided by 128 floats.
__device__ __forceinline__ void matvec32(const float* __restrict__ sW,
                                         const float* __restrict__ vec,
                                         float* __restrict__ dest)
{
    const int lane = threadIdx.x & 31;
    const int warp = threadIdx.x >> 5;
    float4 v0 = *(const float4*)(vec + 0   + lane * 4);
    float4 v1 = *(const float4*)(vec + 128 + lane * 4);
    float4 v2 = *(const float4*)(vec + 256 + lane * 4);
    float4 v3 = *(const float4*)(vec + 384 + lane * 4);
#pragma unroll
    for (int rr = 0; rr < 4; rr++) {
        int r = warp * 4 + rr;
        const float* w = sW + r * 512;
        float4 w0 = *(const float4*)(w + 0   + lane * 4);
        float4 w1 = *(const float4*)(w + 128 + lane * 4);
        float4 w2 = *(const float4*)(w + 256 + lane * 4);
        float4 w3 = *(const float4*)(w + 384 + lane * 4);
        float s = w0.x * v0.x + w0.y * v0.y + w0.z * v0.z + w0.w * v0.w
                + w1.x * v1.x + w1.y * v1.y + w1.z * v1.z + w1.w * v1.w
                + w2.x * v2.x + w2.y * v2.y + w2.z * v2.z + w2.w * v2.w
                + w3.x * v3.x + w3.y * v3.y + w3.z * v3.z + w3.w * v3.w;
#pragma unroll
        for (int off = 16; off >= 1; off >>= 1)
            s += __shfl_down_sync(0xffffffffu, s, off);
        if (lane == 0) dest[r] = s;
    }
}

// softmax over 64 scores -> attn, warp 0 only.
__device__ __forceinline__ void softmax64(const float* __restrict__ score,
                                          float* __restrict__ attn, int t)
{
    if (t < 32) {
        float a = score[t], b = score[t + 32];
        float m = fmaxf(a, b);
#pragma unroll
        for (int off = 16; off >= 1; off >>= 1)
            m = fmaxf(m, __shfl_xor_sync(0xffffffffu, m, off));
        float e0 = __expf(a - m), e1 = __expf(b - m);
        float ss = e0 + e1;
#pragma unroll
        for (int off = 16; off >= 1; off >>= 1)
            ss += __shfl_xor_sync(0xffffffffu, ss, off);
        float inv = 1.f / ss;
        attn[t] = e0 * inv;
        attn[t + 32] = e1 * inv;
    }
}

// ---------------- cluster scan kernel (primary path) ----------------------
struct ClusterSmem {
    float Wh[RPC * 512];      // 64 KB
    float Ww[RPC * 512];      // 64 KB
    float tape[NTAPE * 33];   // padded rows
    float hwork[512];
    float hnew[512];          // assembled via DSMEM pushes
    float rs[CPB * NTAPE];    // per-source-CTA read-score partials
    float ws[CPB * NTAPE];
    float acc[RPC];
    float wv[RPC];
    float rv[RPC];
    float attn[NTAPE];
    float score[NTAPE];
    float bh[RPC], gz[RPC], gr[RPC], gh[RPC], bg[RPC];
};

__global__ __launch_bounds__(NTHREADS, 1) void scan_cluster_kernel(
    const float* __restrict__ tape_init,
    const float* __restrict__ hwork_init,
    const float* __restrict__ W_h,
    const float* __restrict__ b_h,
    const float* __restrict__ W_write,
    const float* __restrict__ gzv,
    const float* __restrict__ grv,
    const float* __restrict__ ghv,
    const float* __restrict__ bgv,
    float* __restrict__ out)
{
    extern __shared__ char raw[];
    ClusterSmem& S = *(ClusterSmem*)raw;

    const int t  = threadIdx.x;
    const int b  = blockIdx.x / CPB;
    const int c  = blockIdx.x % CPB;   // == cluster rank
    const int d0 = c * RPC;
    const float scale = 0.044194173824159216f;  // 1/sqrt(512)

    for (int i = t; i < RPC * 512; i += NTHREADS) {
        S.Wh[i] = W_h[(size_t)d0 * 512 + i];
        S.Ww[i] = W_write[(size_t)d0 * 512 + i];
    }
    for (int i = t; i < NTAPE * RPC; i += NTHREADS) {
        int n = i >> 5, dl = i & 31;
        S.tape[n * 33 + dl] = tape_init[(size_t)(b * NTAPE + n) * DD + d0 + dl];
    }
    for (int i = t; i < 512; i += NTHREADS)
        S.hwork[i] = hwork_init[b * 512 + i];
    if (t < RPC) {
        S.bh[t] = b_h[d0 + t];  S.gz[t] = gzv[d0 + t];
        S.gr[t] = grv[d0 + t];  S.gh[t] = ghv[d0 + t];
        S.bg[t] = bgv[d0 + t];
    }
    __syncthreads();
    CLUSTER_SYNC_();

    const int n4 = t >> 2, q4 = t & 3;
    const int dl8 = t >> 3, q8 = t & 7;
    const uint32_t rs_slot = smem_u32(&S.rs[c * NTAPE]);
    const uint32_t ws_slot = smem_u32(&S.ws[c * NTAPE]);
    const uint32_t hn_slot = smem_u32(&S.hnew[d0]);

    for (int step = 0; step < TT; step++) {
        // prefetch this step's x_proj / z slice (hides DRAM latency under A)
        float xp = 0.f, zt = 0.f;
        if (t < RPC) {
            size_t row = (size_t)(b * TT + step) * EE;
            xp = __ldcs(&g_xz[row + d0 + t]);
            zt = __ldcs(&g_xz[row + 512 + d0 + t]);
        }

        // ---- Phase A: read-score partials (pushed to all peers) + W_h matvec
        {
            float s = 0.f;
#pragma unroll
            for (int k = 0; k < 8; k++) {
                int dl = q4 * 8 + k;
                s += S.hwork[d0 + dl] * S.tape[n4 * 33 + dl];
            }
            s += __shfl_down_sync(0xffffffffu, s, 2);
            s += __shfl_down_sync(0xffffffffu, s, 1);
            if (q4 == 0) {
                uint32_t a = rs_slot + n4 * 4;
#pragma unroll
                for (int r = 0; r < CPB; r++)
                    st_cluster_f32(mapa_u32(a, r), s);
            }
        }
        matvec32(S.Wh, S.hwork, S.acc);
        CLUSTER_SYNC_();

        // ---- Phase B: softmax(read), read_val, h_new (pushed), output ----
        if (t < NTAPE) {
            float s = 0.f;
#pragma unroll
            for (int cc = 0; cc < CPB; cc++)
                s += S.rs[cc * NTAPE + t];
            S.score[t] = s * scale;
        }
        __syncthreads();
        softmax64(S.score, S.attn, t);
        __syncthreads();
        {
            float s = 0.f;
#pragma unroll
            for (int k = 0; k < 8; k++) {
                int n = q8 * 8 + k;
                s += S.attn[n] * S.tape[n * 33 + dl8];
            }
            s += __shfl_down_sync(0xffffffffu, s, 4);
            s += __shfl_down_sync(0xffffffffu, s, 2);
            s += __shfl_down_sync(0xffffffffu, s, 1);
            if (q8 == 0) S.rv[dl8] = s;
        }
        __syncthreads();
        if (t < RPC) {
            float hn = tanhf(xp + S.acc[t] + S.rv[t] + S.bh[t]);
            uint32_t a = hn_slot + t * 4;
#pragma unroll
            for (int r = 0; r < CPB; r++)
                st_cluster_f32(mapa_u32(a, r), hn);
            float gi = zt * S.gz[t] + S.rv[t] * S.gr[t] + hn * S.gh[t] + S.bg[t];
            gi = fminf(fmaxf(gi, -20.f), 20.f);
            float sig = 1.f / (1.f + __expf(-gi));
            out[(size_t)(b * TT + step) * DD + d0 + t] = hn * gi * sig;
        }
        CLUSTER_SYNC_();

        // ---- Phase C: W_write matvec + write-score partials (pushed) ----
        matvec32(S.Ww, S.hnew, S.wv);
        __syncthreads();
        {
            float s = 0.f;
#pragma unroll
            for (int k = 0; k < 8; k++) {
                int dl = q4 * 8 + k;
                s += S.wv[dl] * S.tape[n4 * 33 + dl];
            }
            s += __shfl_down_sync(0xffffffffu, s, 2);
            s += __shfl_down_sync(0xffffffffu, s, 1);
            if (q4 == 0) {
                uint32_t a = ws_slot + n4 * 4;
#pragma unroll
                for (int r = 0; r < CPB; r++)
                    st_cluster_f32(mapa_u32(a, r), s);
            }
        }
        CLUSTER_SYNC_();

        // ---- Phase D: softmax(write), tape update, h_work <- h_new ----
        if (t < NTAPE) {
            float s = 0.f;
#pragma unroll
            for (int cc = 0; cc < CPB; cc++)
                s += S.ws[cc * NTAPE + t];
            S.score[t] = s * scale;
        }
        __syncthreads();
        softmax64(S.score, S.attn, t);
        __syncthreads();
        for (int e = t; e < NTAPE * RPC; e += NTHREADS) {
            int n = e >> 5, dl = e & 31;
            float a  = S.attn[n];
            float tp = S.tape[n * 33 + dl];
            S.tape[n * 33 + dl] = tp - tp * a + S.wv[dl] * a;
        }
        S.hwork[t]       = S.hnew[t];
        S.hwork[t + 256] = S.hnew[t + 256];
        __syncthreads();
    }

    for (int e = t; e < NTAPE * RPC; e += NTHREADS) {
        int n = e >> 5, dl = e & 31;
        out[(size_t)BB * TT * DD + (size_t)(b * NTAPE + n) * DD + d0 + dl] =
            S.tape[n * 33 + dl];
    }
}

// ---------------- fallback scan kernel (global-memory barriers) -----------
struct ScanSmem {
    float Wh[RPC * 512];
    float Ww[RPC * 512];
    float tape[NTAPE * 33];
    float hwork[512];
    float hnew[512];
    float acc[RPC];
    float wv[RPC];
    float rv[RPC];
    float attn[NTAPE];
    float score[NTAPE];
    float bh[RPC], gz[RPC], gr[RPC], gh[RPC], bg[RPC];
};

__global__ __launch_bounds__(NTHREADS, 1) void scan_kernel(
    const float* __restrict__ tape_init,
    const float* __restrict__ hwork_init,
    const float* __restrict__ W_h,
    const float* __restrict__ b_h,
    const float* __restrict__ W_write,
    const float* __restrict__ gzv,
    const float* __restrict__ grv,
    const float* __restrict__ ghv,
    const float* __restrict__ bgv,
    float* __restrict__ out)
{
    extern __shared__ char raw[];
    ScanSmem& S = *(ScanSmem*)raw;

    const int t  = threadIdx.x;
    const int b  = blockIdx.x / CPB;
    const int c  = blockIdx.x % CPB;
    const int d0 = c * RPC;
    const float scale = 0.044194173824159216f;

    for (int i = t; i < RPC * 512; i += NTHREADS) {
        S.Wh[i] = W_h[(size_t)d0 * 512 + i];
        S.Ww[i] = W_write[(size_t)d0 * 512 + i];
    }
    for (int i = t; i < NTAPE * RPC; i += NTHREADS) {
        int n = i >> 5, dl = i & 31;
        S.tape[n * 33 + dl] = tape_init[(size_t)(b * NTAPE + n) * DD + d0 + dl];
    }
    for (int i = t; i < 512; i += NTHREADS)
        S.hwork[i] = hwork_init[b * 512 + i];
    if (t < RPC) {
        S.bh[t] = b_h[d0 + t];  S.gz[t] = gzv[d0 + t];
        S.gr[t] = grv[d0 + t];  S.gh[t] = ghv[d0 + t];
        S.bg[t] = bgv[d0 + t];
    }
    __syncthreads();

    unsigned bc = 0;
    const int n4 = t >> 2, q4 = t & 3;
    const int dl8 = t >> 3, q8 = t & 7;

    for (int step = 0; step < TT; step++) {
        {
            float s = 0.f;
#pragma unroll
            for (int k = 0; k < 8; k++) {
                int dl = q4 * 8 + k;
                s += S.hwork[d0 + dl] * S.tape[n4 * 33 + dl];
            }
            s += __shfl_down_sync(0xffffffffu, s, 2);
            s += __shfl_down_sync(0xffffffffu, s, 1);
            if (q4 == 0) g_rs[(b * CPB + c) * NTAPE + n4] = s;
        }
        matvec32(S.Wh, S.hwork, S.acc);
        batch_barrier(b, (++bc) * CPB);

        if (t < NTAPE) {
            float s = 0.f;
#pragma unroll
            for (int cc = 0; cc < CPB; cc++)
                s += __ldcg(&g_rs[(b * CPB + cc) * NTAPE + t]);
            S.score[t] = s * scale;
        }
        __syncthreads();
        softmax64(S.score, S.attn, t);
        __syncthreads();
        {
            float s = 0.f;
#pragma unroll
            for (int k = 0; k < 8; k++) {
                int n = q8 * 8 + k;
                s += S.attn[n] * S.tape[n * 33 + dl8];
            }
            s += __shfl_down_sync(0xffffffffu, s, 4);
            s += __shfl_down_sync(0xffffffffu, s, 2);
            s += __shfl_down_sync(0xffffffffu, s, 1);
            if (q8 == 0) S.rv[dl8] = s;
        }
        __syncthreads();
        if (t < RPC) {
            size_t row = (size_t)(b * TT + step) * EE;
            float xp = g_xz[row + d0 + t];
            float zt = g_xz[row + 512 + d0 + t];
            float hn = tanhf(xp + S.acc[t] + S.rv[t] + S.bh[t]);
            g_hnew[b * 512 + d0 + t] = hn;
            float gi = zt * S.gz[t] + S.rv[t] * S.gr[t] + hn * S.gh[t] + S.bg[t];
            gi = fminf(fmaxf(gi, -20.f), 20.f);
            float sig = 1.f / (1.f + __expf(-gi));
            out[(size_t)(b * TT + step) * DD + d0 + t] = hn * gi * sig;
        }
        batch_barrier(b, (++bc) * CPB);

        S.hnew[t]       = __ldcg(&g_hnew[b * 512 + t]);
        S.hnew[t + 256] = __ldcg(&g_hnew[b * 512 + t + 256]);
        __syncthreads();
        matvec32(S.Ww, S.hnew, S.wv);
        __syncthreads();
        {
            float s = 0.f;
#pragma unroll
            for (int k = 0; k < 8; k++) {
                int dl = q4 * 8 + k;
                s += S.wv[dl] * S.tape[n4 * 33 + dl];
            }
            s += __shfl_down_sync(0xffffffffu, s, 2);
            s += __shfl_down_sync(0xffffffffu, s, 1);
            if (q4 == 0) g_ws[(b * CPB + c) * NTAPE + n4] = s;
        }
        batch_barrier(b, (++bc) * CPB);

        if (t < NTAPE) {
            float s = 0.f;
#pragma unroll
            for (int cc = 0; cc < CPB; cc++)
                s += __ldcg(&g_ws[(b * CPB + cc) * NTAPE + t]);
            S.score[t] = s * scale;
        }
        __syncthreads();
        softmax64(S.score, S.attn, t);
        __syncthreads();
        for (int e = t; e < NTAPE * RPC; e += NTHREADS) {
            int n = e >> 5, dl = e & 31;
            float a  = S.attn[n];
            float tp = S.tape[n * 33 + dl];
            S.tape[n * 33 + dl] = tp - tp * a + S.wv[dl] * a;
        }
        S.hwork[t]       = S.hnew[t];
        S.hwork[t + 256] = S.hnew[t + 256];
        __syncthreads();
    }

    for (int e = t; e < NTAPE * RPC; e += NTHREADS) {
        int n = e >> 5, dl = e & 31;
        out[(size_t)BB * TT * DD + (size_t)(b * NTAPE + n) * DD + d0 + dl] =
            S.tape[n * 33 + dl];
    }
}

// ---------------- launch ---------------------------------------------------
extern "C" void kernel_launch(void* const* d_in, const int* in_sizes, int n_in,
                              void* d_out, int out_size)
{
    const float* x         = (const float*)d_in[0];
    const float* tape_init = (const float*)d_in[1];
    const float* hwork     = (const float*)d_in[2];
    const float* W_h       = (const float*)d_in[3];
    const float* W_xz      = (const float*)d_in[4];
    const float* b_h       = (const float*)d_in[5];
    const float* W_write   = (const float*)d_in[6];
    const float* g_z       = (const float*)d_in[7];
    const float* g_r       = (const float*)d_in[8];
    const float* g_h       = (const float*)d_in[9];
    const float* b_gate    = (const float*)d_in[10];
    float* out = (float*)d_out;

    gemm_xz_kernel<<<dim3(EE / 64, (BB * TT) / 64), 256>>>(x, W_xz);

    // ---- primary: 16-CTA-cluster scan ----
    cudaFuncSetAttribute(scan_cluster_kernel,
                         cudaFuncAttributeMaxDynamicSharedMemorySize,
                         (int)sizeof(ClusterSmem));
    cudaError_t aerr = cudaFuncSetAttribute(
        scan_cluster_kernel, cudaFuncAttributeNonPortableClusterSizeAllowed, 1);

    cudaLaunchConfig_t cfg = {};
    cfg.gridDim  = dim3(BB * CPB, 1, 1);
    cfg.blockDim = dim3(NTHREADS, 1, 1);
    cfg.dynamicSmemBytes = sizeof(ClusterSmem);
    cfg.stream = 0;

    int maxClu = 0;
    cudaError_t qerr = cudaOccupancyMaxPotentialClusterSize(
        &maxClu, scan_cluster_kernel, &cfg);

    bool launched = false;
    if (aerr == cudaSuccess && qerr == cudaSuccess && maxClu >= CPB) {
        cudaLaunchAttribute attrs[1];
        attrs[0].id = cudaLaunchAttributeClusterDimension;
        attrs[0].val.clusterDim.x = CPB;
        attrs[0].val.clusterDim.y = 1;
        attrs[0].val.clusterDim.z = 1;
        cfg.attrs = attrs;
        cfg.numAttrs = 1;
        cudaError_t lerr = cudaLaunchKernelEx(&cfg, scan_cluster_kernel,
            tape_init, hwork, W_h, b_h, W_write, g_z, g_r, g_h, b_gate, out);
        launched = (lerr == cudaSuccess);
    }

    // ---- fallback: global-memory-barrier scan (verified round-1 path) ----
    if (!launched) {
        cudaFuncSetAttribute(scan_kernel,
                             cudaFuncAttributeMaxDynamicSharedMemorySize,
                             (int)sizeof(ScanSmem));
        init_bar_kernel<<<1, 32>>>();
        scan_kernel<<<BB * CPB, NTHREADS, sizeof(ScanSmem)>>>(
            tape_init, hwork, W_h, b_h, W_write, g_z, g_r, g_h, b_gate, out);
    }
}

// round 3
// speedup vs baseline: 1.2211x; 1.2211x over previous
#include <cuda_runtime.h>
#include <cstdint>
#include <cstddef>

// Problem constants
#define BB   8
#define TT   1024
#define DD   512
#define EE   1024      // 2*D projection width
#define NTAPE 64
#define CPB  16        // CTAs per batch (= cluster size)
#define RPC  32        // rows (and tape cols) per CTA = D / CPB
#define NTHREADS 256

// ---------------- device scratch (static: no allocations allowed) ----------
__device__ float    g_xz[(size_t)BB * TT * EE];     // projected x || z  (33.5 MB)
__device__ float    g_rs[BB * CPB * NTAPE];         // fallback exchange
__device__ float    g_ws[BB * CPB * NTAPE];
__device__ float    g_hnew[BB * DD];
__device__ unsigned g_bar[BB];

__global__ void init_bar_kernel() {
    if (threadIdx.x < BB) g_bar[threadIdx.x] = 0u;
}

// ---------------- projection GEMM: g_xz[m][e] = sum_k X[m][k]*Wxz[e][k] ----
__global__ __launch_bounds__(256) void gemm_xz_kernel(
    const float* __restrict__ X, const float* __restrict__ W)
{
    __shared__ float As[16][68];
    __shared__ float Bs[16][68];

    const int m0 = blockIdx.y * 64;
    const int e0 = blockIdx.x * 64;
    const int tid = threadIdx.x;
    const int tx = tid & 15;
    const int ty = tid >> 4;
    const int lr = tid >> 2;
    const int lc = (tid & 3) * 4;

    float acc[4][4] = {};

    for (int kt = 0; kt < 512; kt += 16) {
        float4 xv = *(const float4*)(X + (size_t)(m0 + lr) * 512 + kt + lc);
        float4 wv = *(const float4*)(W + (size_t)(e0 + lr) * 512 + kt + lc);
        __syncthreads();
        As[lc + 0][lr] = xv.x; As[lc + 1][lr] = xv.y;
        As[lc + 2][lr] = xv.z; As[lc + 3][lr] = xv.w;
        Bs[lc + 0][lr] = wv.x; Bs[lc + 1][lr] = wv.y;
        Bs[lc + 2][lr] = wv.z; Bs[lc + 3][lr] = wv.w;
        __syncthreads();
#pragma unroll
        for (int kk = 0; kk < 16; kk++) {
            float4 a  = *(const float4*)&As[kk][ty * 4];
            float4 bv = *(const float4*)&Bs[kk][tx * 4];
            float av[4] = {a.x, a.y, a.z, a.w};
            float bw[4] = {bv.x, bv.y, bv.z, bv.w};
#pragma unroll
            for (int i = 0; i < 4; i++)
#pragma unroll
                for (int j = 0; j < 4; j++)
                    acc[i][j] += av[i] * bw[j];
        }
    }
#pragma unroll
    for (int i = 0; i < 4; i++) {
        float4 o = make_float4(acc[i][0], acc[i][1], acc[i][2], acc[i][3]);
        *(float4*)(&g_xz[(size_t)(m0 + ty * 4 + i) * EE + e0 + tx * 4]) = o;
    }
}

// ---------------- shared helpers ------------------------------------------
__device__ __forceinline__ uint32_t smem_u32(const void* p) {
    return (uint32_t)__cvta_generic_to_shared(p);
}
__device__ __forceinline__ uint32_t mapa_u32(uint32_t local_addr, uint32_t rank) {
    uint32_t r;
    asm volatile("mapa.shared::cluster.u32 %0, %1, %2;"
                 : "=r"(r) : "r"(local_addr), "r"(rank));
    return r;
}
#define CLUSTER_SYNC_() do {                                              \
    asm volatile("barrier.cluster.arrive.aligned;" ::: "memory");         \
    asm volatile("barrier.cluster.wait.aligned;"   ::: "memory");         \
} while (0)

// st.async: store 4 bytes into remote CTA smem, completing tx on its mbarrier
__device__ __forceinline__ void push_async(uint32_t raddr, float v, uint32_t rmbar) {
    asm volatile(
        "st.async.shared::cluster.mbarrier::complete_tx::bytes.b32 [%0], %1, [%2];"
        :: "r"(raddr), "r"(__float_as_uint(v)), "r"(rmbar) : "memory");
}
__device__ __forceinline__ void mbar_init(uint32_t mbar, uint32_t cnt) {
    asm volatile("mbarrier.init.shared.b64 [%0], %1;" :: "r"(mbar), "r"(cnt) : "memory");
}
__device__ __forceinline__ void mbar_expect_tx(uint32_t mbar, uint32_t bytes) {
    asm volatile("mbarrier.arrive.expect_tx.shared.b64 _, [%0], %1;"
                 :: "r"(mbar), "r"(bytes) : "memory");
}
__device__ __forceinline__ void mbar_wait_parity(uint32_t mbar, uint32_t parity) {
    asm volatile(
        "{\n\t"
        ".reg .pred P1;\n\t"
        "WAIT_LOOP_%=:\n\t"
        "mbarrier.try_wait.parity.acquire.cluster.shared::cta.b64 P1, [%0], %1, 0x989680;\n\t"
        "@P1 bra.uni WAIT_DONE_%=;\n\t"
        "bra.uni WAIT_LOOP_%=;\n\t"
        "WAIT_DONE_%=:\n\t"
        "}"
        :: "r"(mbar), "r"(parity) : "memory");
}

__device__ __forceinline__ unsigned ld_acq_u32(const unsigned* p) {
    unsigned v;
    asm volatile("ld.global.acquire.gpu.u32 %0, [%1];" : "=r"(v) : "l"(p));
    return v;
}
__device__ __forceinline__ void batch_barrier(int b, unsigned target) {
    __syncthreads();
    if (threadIdx.x == 0) {
        __threadfence();
        atomicAdd(&g_bar[b], 1u);
        while (ld_acq_u32(&g_bar[b]) < target) { }
    }
    __syncthreads();
}

// Conflict-free matvec: dest[r] = sum_j sW[r*512+j]*vec[j], r = 0..31.
__device__ __forceinline__ void matvec32(const float* __restrict__ sW,
                                         const float* __restrict__ vec,
                                         float* __restrict__ dest)
{
    const int lane = threadIdx.x & 31;
    const int warp = threadIdx.x >> 5;
    float4 v0 = *(const float4*)(vec + 0   + lane * 4);
    float4 v1 = *(const float4*)(vec + 128 + lane * 4);
    float4 v2 = *(const float4*)(vec + 256 + lane * 4);
    float4 v3 = *(const float4*)(vec + 384 + lane * 4);
#pragma unroll
    for (int rr = 0; rr < 4; rr++) {
        int r = warp * 4 + rr;
        const float* w = sW + r * 512;
        float4 w0 = *(const float4*)(w + 0   + lane * 4);
        float4 w1 = *(const float4*)(w + 128 + lane * 4);
        float4 w2 = *(const float4*)(w + 256 + lane * 4);
        float4 w3 = *(const float4*)(w + 384 + lane * 4);
        float s = w0.x * v0.x + w0.y * v0.y + w0.z * v0.z + w0.w * v0.w
                + w1.x * v1.x + w1.y * v1.y + w1.z * v1.z + w1.w * v1.w
                + w2.x * v2.x + w2.y * v2.y + w2.z * v2.z + w2.w * v2.w
                + w3.x * v3.x + w3.y * v3.y + w3.z * v3.z + w3.w * v3.w;
#pragma unroll
        for (int off = 16; off >= 1; off >>= 1)
            s += __shfl_down_sync(0xffffffffu, s, off);
        if (lane == 0) dest[r] = s;
    }
}

// softmax over 64 scores -> attn, warp 0 only.
__device__ __forceinline__ void softmax64(const float* __restrict__ score,
                                          float* __restrict__ attn, int t)
{
    if (t < 32) {
        float a = score[t], b = score[t + 32];
        float m = fmaxf(a, b);
#pragma unroll
        for (int off = 16; off >= 1; off >>= 1)
            m = fmaxf(m, __shfl_xor_sync(0xffffffffu, m, off));
        float e0 = __expf(a - m), e1 = __expf(b - m);
        float ss = e0 + e1;
#pragma unroll
        for (int off = 16; off >= 1; off >>= 1)
            ss += __shfl_xor_sync(0xffffffffu, ss, off);
        float inv = 1.f / ss;
        attn[t] = e0 * inv;
        attn[t + 32] = e1 * inv;
    }
}

// ---------------- cluster scan kernel (primary path) ----------------------
struct __align__(16) ClusterSmem {
    float Wh[RPC * 512];      // 64 KB
    float Ww[RPC * 512];      // 64 KB
    float tape[NTAPE * 33];
    float hwork[512];
    float hnew[512];          // assembled via st.async pushes
    float rs[CPB * NTAPE];    // per-source-CTA read-score partials
    float ws[CPB * NTAPE];
    float acc[RPC];
    float wv[RPC];
    float rv[RPC];
    float attn[NTAPE];
    float score[NTAPE];
    float bh[RPC], gz[RPC], gr[RPC], gh[RPC], bg[RPC];
    unsigned long long mbar_rs;   // dataflow mbarriers
    unsigned long long mbar_hn;
    unsigned long long mbar_ws;
};

#define RS_BYTES ((CPB - 1) * NTAPE * 4)   // 3840
#define HN_BYTES ((CPB - 1) * RPC * 4)     // 1920
#define WS_BYTES ((CPB - 1) * NTAPE * 4)   // 3840

__global__ __launch_bounds__(NTHREADS, 1) void scan_cluster_kernel(
    const float* __restrict__ tape_init,
    const float* __restrict__ hwork_init,
    const float* __restrict__ W_h,
    const float* __restrict__ b_h,
    const float* __restrict__ W_write,
    const float* __restrict__ gzv,
    const float* __restrict__ grv,
    const float* __restrict__ ghv,
    const float* __restrict__ bgv,
    float* __restrict__ out)
{
    extern __shared__ char raw[];
    ClusterSmem& S = *(ClusterSmem*)raw;

    const int t  = threadIdx.x;
    const int b  = blockIdx.x / CPB;
    const int c  = blockIdx.x % CPB;   // cluster rank
    const int d0 = c * RPC;
    const float scale = 0.044194173824159216f;  // 1/sqrt(512)

    for (int i = t; i < RPC * 512; i += NTHREADS) {
        S.Wh[i] = W_h[(size_t)d0 * 512 + i];
        S.Ww[i] = W_write[(size_t)d0 * 512 + i];
    }
    for (int i = t; i < NTAPE * RPC; i += NTHREADS) {
        int n = i >> 5, dl = i & 31;
        S.tape[n * 33 + dl] = tape_init[(size_t)(b * NTAPE + n) * DD + d0 + dl];
    }
    for (int i = t; i < 512; i += NTHREADS)
        S.hwork[i] = hwork_init[b * 512 + i];
    if (t < RPC) {
        S.bh[t] = b_h[d0 + t];  S.gz[t] = gzv[d0 + t];
        S.gr[t] = grv[d0 + t];  S.gh[t] = ghv[d0 + t];
        S.bg[t] = bgv[d0 + t];
    }
    const uint32_t mb_rs = smem_u32(&S.mbar_rs);
    const uint32_t mb_hn = smem_u32(&S.mbar_hn);
    const uint32_t mb_ws = smem_u32(&S.mbar_ws);
    if (t == 0) {
        mbar_init(mb_rs, 1);
        mbar_init(mb_hn, 1);
        mbar_init(mb_ws, 1);
        mbar_expect_tx(mb_rs, RS_BYTES);   // arm for step 0
        mbar_expect_tx(mb_hn, HN_BYTES);
        mbar_expect_tx(mb_ws, WS_BYTES);
    }
    __syncthreads();
    CLUSTER_SYNC_();   // all inits visible cluster-wide before any st.async

    const int n4 = t >> 2, q4 = t & 3;
    const int dl8 = t >> 3, q8 = t & 7;
    // local smem byte addresses of my slots in each exchange buffer
    const uint32_t rs_slot = smem_u32(&S.rs[c * NTAPE]);   // + n4*4
    const uint32_t ws_slot = smem_u32(&S.ws[c * NTAPE]);
    const uint32_t hn_slot = smem_u32(&S.hnew[d0]);        // + t*4

    for (int step = 0; step < TT; step++) {
        const uint32_t par = step & 1u;

        // prefetch this step's x_proj / z slice
        float xp = 0.f, zt = 0.f;
        if (t < RPC) {
            size_t row = (size_t)(b * TT + step) * EE;
            xp = __ldcs(&g_xz[row + d0 + t]);
            zt = __ldcs(&g_xz[row + 512 + d0 + t]);
        }

        // ---- Phase A: read-score partials (async pushes) + W_h matvec ----
        {
            float s = 0.f;
#pragma unroll
            for (int k = 0; k < 8; k++) {
                int dl = q4 * 8 + k;
                s += S.hwork[d0 + dl] * S.tape[n4 * 33 + dl];
            }
            s += __shfl_down_sync(0xffffffffu, s, 2);
            s += __shfl_down_sync(0xffffffffu, s, 1);
            if (q4 == 0) {
                uint32_t a = rs_slot + n4 * 4;
#pragma unroll
                for (int r = 0; r < CPB; r++) {
                    if (r == c) continue;
                    push_async(mapa_u32(a, r), s, mapa_u32(mb_rs, r));
                }
                S.rs[c * NTAPE + n4] = s;   // own slot: plain STS
            }
        }
        matvec32(S.Wh, S.hwork, S.acc);
        mbar_wait_parity(mb_rs, par);
        __syncthreads();
        if (t == 0) mbar_expect_tx(mb_rs, RS_BYTES);   // re-arm for next step

        // ---- Phase B: softmax(read), read_val, h_new (pushed), output ----
        if (t < NTAPE) {
            float s = 0.f;
#pragma unroll
            for (int cc = 0; cc < CPB; cc++)
                s += S.rs[cc * NTAPE + t];
            S.score[t] = s * scale;
        }
        __syncthreads();
        softmax64(S.score, S.attn, t);
        __syncthreads();
        {
            float s = 0.f;
#pragma unroll
            for (int k = 0; k < 8; k++) {
                int n = q8 * 8 + k;
                s += S.attn[n] * S.tape[n * 33 + dl8];
            }
            s += __shfl_down_sync(0xffffffffu, s, 4);
            s += __shfl_down_sync(0xffffffffu, s, 2);
            s += __shfl_down_sync(0xffffffffu, s, 1);
            if (q8 == 0) S.rv[dl8] = s;
        }
        __syncthreads();
        if (t < RPC) {
            float hn = tanhf(xp + S.acc[t] + S.rv[t] + S.bh[t]);
            uint32_t a = hn_slot + t * 4;
#pragma unroll
            for (int r = 0; r < CPB; r++) {
                if (r == c) continue;
                push_async(mapa_u32(a, r), hn, mapa_u32(mb_hn, r));
            }
            S.hnew[d0 + t] = hn;   // own slot
            float gi = zt * S.gz[t] + S.rv[t] * S.gr[t] + hn * S.gh[t] + S.bg[t];
            gi = fminf(fmaxf(gi, -20.f), 20.f);
            float sig = 1.f / (1.f + __expf(-gi));
            out[(size_t)(b * TT + step) * DD + d0 + t] = hn * gi * sig;
        }
        mbar_wait_parity(mb_hn, par);
        __syncthreads();
        if (t == 0) mbar_expect_tx(mb_hn, HN_BYTES);

        // ---- Phase C: W_write matvec + write-score partials (pushed) ----
        matvec32(S.Ww, S.hnew, S.wv);
        __syncthreads();
        {
            float s = 0.f;
#pragma unroll
            for (int k = 0; k < 8; k++) {
                int dl = q4 * 8 + k;
                s += S.wv[dl] * S.tape[n4 * 33 + dl];
            }
            s += __shfl_down_sync(0xffffffffu, s, 2);
            s += __shfl_down_sync(0xffffffffu, s, 1);
            if (q4 == 0) {
                uint32_t a = ws_slot + n4 * 4;
#pragma unroll
                for (int r = 0; r < CPB; r++) {
                    if (r == c) continue;
                    push_async(mapa_u32(a, r), s, mapa_u32(mb_ws, r));
                }
                S.ws[c * NTAPE + n4] = s;
            }
        }
        mbar_wait_parity(mb_ws, par);
        __syncthreads();
        if (t == 0) mbar_expect_tx(mb_ws, WS_BYTES);

        // ---- Phase D: softmax(write), tape update, h_work <- h_new ----
        if (t < NTAPE) {
            float s = 0.f;
#pragma unroll
            for (int cc = 0; cc < CPB; cc++)
                s += S.ws[cc * NTAPE + t];
            S.score[t] = s * scale;
        }
        __syncthreads();
        softmax64(S.score, S.attn, t);
        __syncthreads();
        for (int e = t; e < NTAPE * RPC; e += NTHREADS) {
            int n = e >> 5, dl = e & 31;
            float a  = S.attn[n];
            float tp = S.tape[n * 33 + dl];
            S.tape[n * 33 + dl] = tp - tp * a + S.wv[dl] * a;
        }
        S.hwork[t]       = S.hnew[t];
        S.hwork[t + 256] = S.hnew[t + 256];
        __syncthreads();
    }

    for (int e = t; e < NTAPE * RPC; e += NTHREADS) {
        int n = e >> 5, dl = e & 31;
        out[(size_t)BB * TT * DD + (size_t)(b * NTAPE + n) * DD + d0 + dl] =
            S.tape[n * 33 + dl];
    }
    CLUSTER_SYNC_();   // no CTA exits while peers might still target its smem
}

// ---------------- fallback scan kernel (global-memory barriers) -----------
struct ScanSmem {
    float Wh[RPC * 512];
    float Ww[RPC * 512];
    float tape[NTAPE * 33];
    float hwork[512];
    float hnew[512];
    float acc[RPC];
    float wv[RPC];
    float rv[RPC];
    float attn[NTAPE];
    float score[NTAPE];
    float bh[RPC], gz[RPC], gr[RPC], gh[RPC], bg[RPC];
};

__global__ __launch_bounds__(NTHREADS, 1) void scan_kernel(
    const float* __restrict__ tape_init,
    const float* __restrict__ hwork_init,
    const float* __restrict__ W_h,
    const float* __restrict__ b_h,
    const float* __restrict__ W_write,
    const float* __restrict__ gzv,
    const float* __restrict__ grv,
    const float* __restrict__ ghv,
    const float* __restrict__ bgv,
    float* __restrict__ out)
{
    extern __shared__ char raw[];
    ScanSmem& S = *(ScanSmem*)raw;

    const int t  = threadIdx.x;
    const int b  = blockIdx.x / CPB;
    const int c  = blockIdx.x % CPB;
    const int d0 = c * RPC;
    const float scale = 0.044194173824159216f;

    for (int i = t; i < RPC * 512; i += NTHREADS) {
        S.Wh[i] = W_h[(size_t)d0 * 512 + i];
        S.Ww[i] = W_write[(size_t)d0 * 512 + i];
    }
    for (int i = t; i < NTAPE * RPC; i += NTHREADS) {
        int n = i >> 5, dl = i & 31;
        S.tape[n * 33 + dl] = tape_init[(size_t)(b * NTAPE + n) * DD + d0 + dl];
    }
    for (int i = t; i < 512; i += NTHREADS)
        S.hwork[i] = hwork_init[b * 512 + i];
    if (t < RPC) {
        S.bh[t] = b_h[d0 + t];  S.gz[t] = gzv[d0 + t];
        S.gr[t] = grv[d0 + t];  S.gh[t] = ghv[d0 + t];
        S.bg[t] = bgv[d0 + t];
    }
    __syncthreads();

    unsigned bc = 0;
    const int n4 = t >> 2, q4 = t & 3;
    const int dl8 = t >> 3, q8 = t & 7;

    for (int step = 0; step < TT; step++) {
        {
            float s = 0.f;
#pragma unroll
            for (int k = 0; k < 8; k++) {
                int dl = q4 * 8 + k;
                s += S.hwork[d0 + dl] * S.tape[n4 * 33 + dl];
            }
            s += __shfl_down_sync(0xffffffffu, s, 2);
            s += __shfl_down_sync(0xffffffffu, s, 1);
            if (q4 == 0) g_rs[(b * CPB + c) * NTAPE + n4] = s;
        }
        matvec32(S.Wh, S.hwork, S.acc);
        batch_barrier(b, (++bc) * CPB);

        if (t < NTAPE) {
            float s = 0.f;
#pragma unroll
            for (int cc = 0; cc < CPB; cc++)
                s += __ldcg(&g_rs[(b * CPB + cc) * NTAPE + t]);
            S.score[t] = s * scale;
        }
        __syncthreads();
        softmax64(S.score, S.attn, t);
        __syncthreads();
        {
            float s = 0.f;
#pragma unroll
            for (int k = 0; k < 8; k++) {
                int n = q8 * 8 + k;
                s += S.attn[n] * S.tape[n * 33 + dl8];
            }
            s += __shfl_down_sync(0xffffffffu, s, 4);
            s += __shfl_down_sync(0xffffffffu, s, 2);
            s += __shfl_down_sync(0xffffffffu, s, 1);
            if (q8 == 0) S.rv[dl8] = s;
        }
        __syncthreads();
        if (t < RPC) {
            size_t row = (size_t)(b * TT + step) * EE;
            float xp = g_xz[row + d0 + t];
            float zt = g_xz[row + 512 + d0 + t];
            float hn = tanhf(xp + S.acc[t] + S.rv[t] + S.bh[t]);
            g_hnew[b * 512 + d0 + t] = hn;
            float gi = zt * S.gz[t] + S.rv[t] * S.gr[t] + hn * S.gh[t] + S.bg[t];
            gi = fminf(fmaxf(gi, -20.f), 20.f);
            float sig = 1.f / (1.f + __expf(-gi));
            out[(size_t)(b * TT + step) * DD + d0 + t] = hn * gi * sig;
        }
        batch_barrier(b, (++bc) * CPB);

        S.hnew[t]       = __ldcg(&g_hnew[b * 512 + t]);
        S.hnew[t + 256] = __ldcg(&g_hnew[b * 512 + t + 256]);
        __syncthreads();
        matvec32(S.Ww, S.hnew, S.wv);
        __syncthreads();
        {
            float s = 0.f;
#pragma unroll
            for (int k = 0; k < 8; k++) {
                int dl = q4 * 8 + k;
                s += S.wv[dl] * S.tape[n4 * 33 + dl];
            }
            s += __shfl_down_sync(0xffffffffu, s, 2);
            s += __shfl_down_sync(0xffffffffu, s, 1);
            if (q4 == 0) g_ws[(b * CPB + c) * NTAPE + n4] = s;
        }
        batch_barrier(b, (++bc) * CPB);

        if (t < NTAPE) {
            float s = 0.f;
#pragma unroll
            for (int cc = 0; cc < CPB; cc++)
                s += __ldcg(&g_ws[(b * CPB + cc) * NTAPE + t]);
            S.score[t] = s * scale;
        }
        __syncthreads();
        softmax64(S.score, S.attn, t);
        __syncthreads();
        for (int e = t; e < NTAPE * RPC; e += NTHREADS) {
            int n = e >> 5, dl = e & 31;
            float a  = S.attn[n];
            float tp = S.tape[n * 33 + dl];
            S.tape[n * 33 + dl] = tp - tp * a + S.wv[dl] * a;
        }
        S.hwork[t]       = S.hnew[t];
        S.hwork[t + 256] = S.hnew[t + 256];
        __syncthreads();
    }

    for (int e = t; e < NTAPE * RPC; e += NTHREADS) {
        int n = e >> 5, dl = e & 31;
        out[(size_t)BB * TT * DD + (size_t)(b * NTAPE + n) * DD + d0 + dl] =
            S.tape[n * 33 + dl];
    }
}

// ---------------- launch ---------------------------------------------------
extern "C" void kernel_launch(void* const* d_in, const int* in_sizes, int n_in,
                              void* d_out, int out_size)
{
    const float* x         = (const float*)d_in[0];
    const float* tape_init = (const float*)d_in[1];
    const float* hwork     = (const float*)d_in[2];
    const float* W_h       = (const float*)d_in[3];
    const float* W_xz      = (const float*)d_in[4];
    const float* b_h       = (const float*)d_in[5];
    const float* W_write   = (const float*)d_in[6];
    const float* g_z       = (const float*)d_in[7];
    const float* g_r       = (const float*)d_in[8];
    const float* g_h       = (const float*)d_in[9];
    const float* b_gate    = (const float*)d_in[10];
    float* out = (float*)d_out;

    gemm_xz_kernel<<<dim3(EE / 64, (BB * TT) / 64), 256>>>(x, W_xz);

    // ---- primary: 16-CTA-cluster scan with mbarrier dataflow sync ----
    cudaFuncSetAttribute(scan_cluster_kernel,
                         cudaFuncAttributeMaxDynamicSharedMemorySize,
                         (int)sizeof(ClusterSmem));
    cudaError_t aerr = cudaFuncSetAttribute(
        scan_cluster_kernel, cudaFuncAttributeNonPortableClusterSizeAllowed, 1);

    cudaLaunchConfig_t cfg = {};
    cfg.gridDim  = dim3(BB * CPB, 1, 1);
    cfg.blockDim = dim3(NTHREADS, 1, 1);
    cfg.dynamicSmemBytes = sizeof(ClusterSmem);
    cfg.stream = 0;

    int maxClu = 0;
    cudaError_t qerr = cudaOccupancyMaxPotentialClusterSize(
        &maxClu, scan_cluster_kernel, &cfg);

    bool launched = false;
    if (aerr == cudaSuccess && qerr == cudaSuccess && maxClu >= CPB) {
        cudaLaunchAttribute attrs[1];
        attrs[0].id = cudaLaunchAttributeClusterDimension;
        attrs[0].val.clusterDim.x = CPB;
        attrs[0].val.clusterDim.y = 1;
        attrs[0].val.clusterDim.z = 1;
        cfg.attrs = attrs;
        cfg.numAttrs = 1;
        cudaError_t lerr = cudaLaunchKernelEx(&cfg, scan_cluster_kernel,
            tape_init, hwork, W_h, b_h, W_write, g_z, g_r, g_h, b_gate, out);
        launched = (lerr == cudaSuccess);
    }

    // ---- fallback: global-memory-barrier scan ----
    if (!launched) {
        cudaFuncSetAttribute(scan_kernel,
                             cudaFuncAttributeMaxDynamicSharedMemorySize,
                             (int)sizeof(ScanSmem));
        init_bar_kernel<<<1, 32>>>();
        scan_kernel<<<BB * CPB, NTHREADS, sizeof(ScanSmem)>>>(
            tape_init, hwork, W_h, b_h, W_write, g_z, g_r, g_h, b_gate, out);
    }
}

// round 4
// speedup vs baseline: 1.5344x; 1.2566x over previous
#include <cuda_runtime.h>
#include <cstdint>
#include <cstddef>

// Problem constants
#define BB   8
#define TT   1024
#define DD   512
#define EE   1024
#define NTAPE 64
#define CPB  16        // CTAs per cluster
#define RPC  32        // rows / tape-cols per CTA
#define NTHREADS 256
#define NCLU  4        // clusters (2 batches each)

// ---------------- device scratch ----------
__device__ float    g_xz[(size_t)BB * TT * EE];
__device__ float    g_rs[BB * CPB * NTAPE];         // fallback exchange
__device__ float    g_ws[BB * CPB * NTAPE];
__device__ float    g_hnew[BB * DD];
__device__ unsigned g_bar[BB];

__global__ void init_bar_kernel() {
    if (threadIdx.x < BB) g_bar[threadIdx.x] = 0u;
}

// ---------------- projection GEMM ----------
__global__ __launch_bounds__(256) void gemm_xz_kernel(
    const float* __restrict__ X, const float* __restrict__ W)
{
    __shared__ float As[16][68];
    __shared__ float Bs[16][68];
    const int m0 = blockIdx.y * 64;
    const int e0 = blockIdx.x * 64;
    const int tid = threadIdx.x;
    const int tx = tid & 15;
    const int ty = tid >> 4;
    const int lr = tid >> 2;
    const int lc = (tid & 3) * 4;
    float acc[4][4] = {};
    for (int kt = 0; kt < 512; kt += 16) {
        float4 xv = *(const float4*)(X + (size_t)(m0 + lr) * 512 + kt + lc);
        float4 wv = *(const float4*)(W + (size_t)(e0 + lr) * 512 + kt + lc);
        __syncthreads();
        As[lc + 0][lr] = xv.x; As[lc + 1][lr] = xv.y;
        As[lc + 2][lr] = xv.z; As[lc + 3][lr] = xv.w;
        Bs[lc + 0][lr] = wv.x; Bs[lc + 1][lr] = wv.y;
        Bs[lc + 2][lr] = wv.z; Bs[lc + 3][lr] = wv.w;
        __syncthreads();
#pragma unroll
        for (int kk = 0; kk < 16; kk++) {
            float4 a  = *(const float4*)&As[kk][ty * 4];
            float4 bv = *(const float4*)&Bs[kk][tx * 4];
            float av[4] = {a.x, a.y, a.z, a.w};
            float bw[4] = {bv.x, bv.y, bv.z, bv.w};
#pragma unroll
            for (int i = 0; i < 4; i++)
#pragma unroll
                for (int j = 0; j < 4; j++)
                    acc[i][j] += av[i] * bw[j];
        }
    }
#pragma unroll
    for (int i = 0; i < 4; i++) {
        float4 o = make_float4(acc[i][0], acc[i][1], acc[i][2], acc[i][3]);
        *(float4*)(&g_xz[(size_t)(m0 + ty * 4 + i) * EE + e0 + tx * 4]) = o;
    }
}

// ---------------- helpers ------------------------------------------
__device__ __forceinline__ uint32_t smem_u32(const void* p) {
    return (uint32_t)__cvta_generic_to_shared(p);
}
__device__ __forceinline__ uint32_t mapa_u32(uint32_t local_addr, uint32_t rank) {
    uint32_t r;
    asm volatile("mapa.shared::cluster.u32 %0, %1, %2;"
                 : "=r"(r) : "r"(local_addr), "r"(rank));
    return r;
}
#define CLUSTER_SYNC_() do {                                              \
    asm volatile("barrier.cluster.arrive.aligned;" ::: "memory");         \
    asm volatile("barrier.cluster.wait.aligned;"   ::: "memory");         \
} while (0)

__device__ __forceinline__ void push_async(uint32_t raddr, float v, uint32_t rmbar) {
    asm volatile(
        "st.async.shared::cluster.mbarrier::complete_tx::bytes.b32 [%0], %1, [%2];"
        :: "r"(raddr), "r"(__float_as_uint(v)), "r"(rmbar) : "memory");
}
__device__ __forceinline__ void mbar_init(uint32_t mbar, uint32_t cnt) {
    asm volatile("mbarrier.init.shared.b64 [%0], %1;" :: "r"(mbar), "r"(cnt) : "memory");
}
__device__ __forceinline__ void mbar_expect_tx(uint32_t mbar, uint32_t bytes) {
    asm volatile("mbarrier.arrive.expect_tx.shared.b64 _, [%0], %1;"
                 :: "r"(mbar), "r"(bytes) : "memory");
}
__device__ __forceinline__ void mbar_wait_cta(uint32_t mbar, uint32_t parity) {
    asm volatile(
        "{\n\t"
        ".reg .pred P1;\n\t"
        "WAIT_LOOP_%=:\n\t"
        "mbarrier.try_wait.parity.acquire.cta.shared::cta.b64 P1, [%0], %1, 0x989680;\n\t"
        "@P1 bra.uni WAIT_DONE_%=;\n\t"
        "bra.uni WAIT_LOOP_%=;\n\t"
        "WAIT_DONE_%=:\n\t"
        "}"
        :: "r"(mbar), "r"(parity) : "memory");
}

__device__ __forceinline__ unsigned ld_acq_u32(const unsigned* p) {
    unsigned v;
    asm volatile("ld.global.acquire.gpu.u32 %0, [%1];" : "=r"(v) : "l"(p));
    return v;
}
__device__ __forceinline__ void batch_barrier(int b, unsigned target) {
    __syncthreads();
    if (threadIdx.x == 0) {
        __threadfence();
        atomicAdd(&g_bar[b], 1u);
        while (ld_acq_u32(&g_bar[b]) < target) { }
    }
    __syncthreads();
}

// Conflict-free matvec: dest[r] = sum_j sW[r*512+j]*vec[j], r=0..31.
__device__ __forceinline__ void matvec32(const float* __restrict__ sW,
                                         const float* __restrict__ vec,
                                         float* __restrict__ dest)
{
    const int lane = threadIdx.x & 31;
    const int warp = threadIdx.x >> 5;
    float4 v0 = *(const float4*)(vec + 0   + lane * 4);
    float4 v1 = *(const float4*)(vec + 128 + lane * 4);
    float4 v2 = *(const float4*)(vec + 256 + lane * 4);
    float4 v3 = *(const float4*)(vec + 384 + lane * 4);
#pragma unroll
    for (int rr = 0; rr < 4; rr++) {
        int r = warp * 4 + rr;
        const float* w = sW + r * 512;
        float4 w0 = *(const float4*)(w + 0   + lane * 4);
        float4 w1 = *(const float4*)(w + 128 + lane * 4);
        float4 w2 = *(const float4*)(w + 256 + lane * 4);
        float4 w3 = *(const float4*)(w + 384 + lane * 4);
        float s = w0.x * v0.x + w0.y * v0.y + w0.z * v0.z + w0.w * v0.w
                + w1.x * v1.x + w1.y * v1.y + w1.z * v1.z + w1.w * v1.w
                + w2.x * v2.x + w2.y * v2.y + w2.z * v2.z + w2.w * v2.w
                + w3.x * v3.x + w3.y * v3.y + w3.z * v3.z + w3.w * v3.w;
#pragma unroll
        for (int off = 16; off >= 1; off >>= 1)
            s += __shfl_down_sync(0xffffffffu, s, off);
        if (lane == 0) dest[r] = s;
    }
}

// ---------------- dual-batch cluster scan kernel ---------------------------
struct __align__(16) CS {
    float Wh[RPC * 512];          // 64 KB (shared across both batches)
    float Ww[RPC * 512];          // 64 KB
    float tape[2][NTAPE * 33];
    float hwork[2][512];
    float hnew[2][512];
    float rs[2][CPB * NTAPE];
    float ws[2][CPB * NTAPE];
    float acc[2][RPC];
    float wv[2][RPC];
    float attn[2][NTAPE];
    float bh[RPC], gz[RPC], gr[RPC], gh[RPC], bg[RPC];
    unsigned long long mb_rs[2], mb_hn[2], mb_ws[2];
};

#define RS_BYTES ((CPB - 1) * NTAPE * 4)   // 3840
#define HN_BYTES ((CPB - 1) * RPC * 4)     // 1920
#define WS_BYTES ((CPB - 1) * NTAPE * 4)

__global__ __launch_bounds__(NTHREADS, 1) void scan2_kernel(
    const float* __restrict__ tape_init,
    const float* __restrict__ hwork_init,
    const float* __restrict__ W_h,
    const float* __restrict__ b_h,
    const float* __restrict__ W_write,
    const float* __restrict__ gzv,
    const float* __restrict__ grv,
    const float* __restrict__ ghv,
    const float* __restrict__ bgv,
    float* __restrict__ out)
{
    extern __shared__ char raw[];
    CS& S = *(CS*)raw;

    const int t    = threadIdx.x;
    const int lane = t & 31;
    const int cw   = t >> 5;
    const int u    = blockIdx.x >> 4;     // cluster index (batch pair)
    const int c    = blockIdx.x & 15;     // cluster rank
    const int d0   = c * RPC;
    const float scale = 0.044194173824159216f;  // 1/sqrt(512)

    // control warps: warp0 <-> batch g=0, warp5 <-> batch g=1 (different SMSPs)
    const bool isctrl = (cw == 0) || (cw == 5);
    const int  gme    = (cw == 5) ? 1 : 0;

    // ---- one-time loads ----
    for (int i = t; i < RPC * 512; i += NTHREADS) {
        S.Wh[i] = W_h[(size_t)d0 * 512 + i];
        S.Ww[i] = W_write[(size_t)d0 * 512 + i];
    }
#pragma unroll
    for (int g = 0; g < 2; g++) {
        int bg = 2 * u + g;
        for (int i = t; i < NTAPE * RPC; i += NTHREADS) {
            int n = i >> 5, dl = i & 31;
            S.tape[g][n * 33 + dl] = tape_init[(size_t)(bg * NTAPE + n) * DD + d0 + dl];
        }
        for (int i = t; i < 512; i += NTHREADS)
            S.hwork[g][i] = hwork_init[bg * 512 + i];
    }
    if (t < RPC) {
        S.bh[t] = b_h[d0 + t];  S.gz[t] = gzv[d0 + t];
        S.gr[t] = grv[d0 + t];  S.gh[t] = ghv[d0 + t];
        S.bg[t] = bgv[d0 + t];
    }

    const uint32_t sbase = smem_u32(&S);
    uint32_t mbrs[2], mbhn[2], mbws[2];
    uint32_t off_rs[2], off_hn[2], off_ws[2];
    uint32_t off_mbrs[2], off_mbhn[2], off_mbws[2];
#pragma unroll
    for (int g = 0; g < 2; g++) {
        mbrs[g] = smem_u32(&S.mb_rs[g]);
        mbhn[g] = smem_u32(&S.mb_hn[g]);
        mbws[g] = smem_u32(&S.mb_ws[g]);
        off_rs[g] = smem_u32(&S.rs[g][0]) - sbase;
        off_hn[g] = smem_u32(&S.hnew[g][0]) - sbase;
        off_ws[g] = smem_u32(&S.ws[g][0]) - sbase;
        off_mbrs[g] = mbrs[g] - sbase;
        off_mbhn[g] = mbhn[g] - sbase;
        off_mbws[g] = mbws[g] - sbase;
    }
    if (t == 0) {
#pragma unroll
        for (int g = 0; g < 2; g++) {
            mbar_init(mbrs[g], 1); mbar_init(mbhn[g], 1); mbar_init(mbws[g], 1);
            mbar_expect_tx(mbrs[g], RS_BYTES);
            mbar_expect_tx(mbhn[g], HN_BYTES);
            mbar_expect_tx(mbws[g], WS_BYTES);
        }
    }
    __syncthreads();
    CLUSTER_SYNC_();

    const int n4 = t >> 2, q4 = t & 3;

    for (int step = 0; step < TT; step++) {
        const uint32_t par = step & 1u;

        // ---- prefetch xz (control warps, registers) ----
        float xp = 0.f, zt = 0.f;
        if (isctrl) {
            size_t row = (size_t)((2 * u + gme) * TT + step) * EE;
            xp = __ldcs(&g_xz[row + d0 + lane]);
            zt = __ldcs(&g_xz[row + 512 + d0 + lane]);
        }

        // ---- Phase A (both batches): read-score partials + Wh matvec ----
#pragma unroll
        for (int g = 0; g < 2; g++) {
            float s = 0.f;
#pragma unroll
            for (int k = 0; k < 8; k++) {
                int dl = q4 * 8 + k;
                s += S.hwork[g][d0 + dl] * S.tape[g][n4 * 33 + dl];
            }
            s += __shfl_down_sync(0xffffffffu, s, 2);
            s += __shfl_down_sync(0xffffffffu, s, 1);
            if (q4 == 0) {
                S.rs[g][c * NTAPE + n4] = s;
                uint32_t doff = off_rs[g] + (uint32_t)(c * NTAPE + n4) * 4;
#pragma unroll
                for (int r = 0; r < CPB; r++) {
                    if (r == c) continue;
                    uint32_t pb = mapa_u32(sbase, r);
                    push_async(pb + doff, s, pb + off_mbrs[g]);
                }
            }
            matvec32(S.Wh, S.hwork[g], S.acc[g]);
        }
        __syncthreads();   // S1

        // ---- Phase B (control warps, solo): softmax/read_val/h_new/out ----
        if (isctrl) {
            const int g = gme;
            const int bg = 2 * u + g;
            mbar_wait_cta(mbrs[g], par);
            if (lane == 0) mbar_expect_tx(mbrs[g], RS_BYTES);
            float a0 = 0.f, a1 = 0.f;
#pragma unroll
            for (int cc = 0; cc < CPB; cc++) {
                a0 += S.rs[g][cc * NTAPE + lane];
                a1 += S.rs[g][cc * NTAPE + lane + 32];
            }
            a0 *= scale; a1 *= scale;
            float m = fmaxf(a0, a1);
#pragma unroll
            for (int off = 16; off >= 1; off >>= 1)
                m = fmaxf(m, __shfl_xor_sync(0xffffffffu, m, off));
            float e0 = __expf(a0 - m), e1 = __expf(a1 - m);
            float ss = e0 + e1;
#pragma unroll
            for (int off = 16; off >= 1; off >>= 1)
                ss += __shfl_xor_sync(0xffffffffu, ss, off);
            float inv = 1.f / ss;
            e0 *= inv; e1 *= inv;
            // read_val[lane] via shfl broadcast of attn
            float rv = 0.f;
#pragma unroll
            for (int n = 0; n < 32; n++)
                rv += __shfl_sync(0xffffffffu, e0, n) * S.tape[g][n * 33 + lane];
#pragma unroll
            for (int n = 0; n < 32; n++)
                rv += __shfl_sync(0xffffffffu, e1, n) * S.tape[g][(n + 32) * 33 + lane];
            float pre = xp + S.acc[g][lane] + rv + S.bh[lane];
            float ex2 = __expf(2.f * pre);
            float hn  = 1.f - 2.f / (ex2 + 1.f);   // tanh
            S.hnew[g][d0 + lane] = hn;
            uint32_t doff = off_hn[g] + (uint32_t)(d0 + lane) * 4;
#pragma unroll
            for (int r = 0; r < CPB; r++) {
                if (r == c) continue;
                uint32_t pb = mapa_u32(sbase, r);
                push_async(pb + doff, hn, pb + off_mbhn[g]);
            }
            float gi = zt * S.gz[lane] + rv * S.gr[lane] + hn * S.gh[lane] + S.bg[lane];
            gi = fminf(fmaxf(gi, -20.f), 20.f);
            float sig = 1.f / (1.f + __expf(-gi));
            out[(size_t)(bg * TT + step) * DD + d0 + lane] = hn * gi * sig;
            // wait for full hnew of my batch
            mbar_wait_cta(mbhn[g], par);
            if (lane == 0) mbar_expect_tx(mbhn[g], HN_BYTES);
        }
        __syncthreads();   // S2

        // ---- Phase C: Ww matvecs (both batches) ----
        matvec32(S.Ww, S.hnew[0], S.wv[0]);
        matvec32(S.Ww, S.hnew[1], S.wv[1]);
        __syncthreads();   // S3

        // ---- write-score partials (both batches) ----
#pragma unroll
        for (int g = 0; g < 2; g++) {
            float s = 0.f;
#pragma unroll
            for (int k = 0; k < 8; k++) {
                int dl = q4 * 8 + k;
                s += S.wv[g][dl] * S.tape[g][n4 * 33 + dl];
            }
            s += __shfl_down_sync(0xffffffffu, s, 2);
            s += __shfl_down_sync(0xffffffffu, s, 1);
            if (q4 == 0) {
                S.ws[g][c * NTAPE + n4] = s;
                uint32_t doff = off_ws[g] + (uint32_t)(c * NTAPE + n4) * 4;
#pragma unroll
                for (int r = 0; r < CPB; r++) {
                    if (r == c) continue;
                    uint32_t pb = mapa_u32(sbase, r);
                    push_async(pb + doff, s, pb + off_mbws[g]);
                }
            }
        }
        __syncthreads();   // S4

        // ---- write softmax (control warps) ----
        if (isctrl) {
            const int g = gme;
            mbar_wait_cta(mbws[g], par);
            if (lane == 0) mbar_expect_tx(mbws[g], WS_BYTES);
            float a0 = 0.f, a1 = 0.f;
#pragma unroll
            for (int cc = 0; cc < CPB; cc++) {
                a0 += S.ws[g][cc * NTAPE + lane];
                a1 += S.ws[g][cc * NTAPE + lane + 32];
            }
            a0 *= scale; a1 *= scale;
            float m = fmaxf(a0, a1);
#pragma unroll
            for (int off = 16; off >= 1; off >>= 1)
                m = fmaxf(m, __shfl_xor_sync(0xffffffffu, m, off));
            float e0 = __expf(a0 - m), e1 = __expf(a1 - m);
            float ss = e0 + e1;
#pragma unroll
            for (int off = 16; off >= 1; off >>= 1)
                ss += __shfl_xor_sync(0xffffffffu, ss, off);
            float inv = 1.f / ss;
            S.attn[g][lane]      = e0 * inv;
            S.attn[g][lane + 32] = e1 * inv;
        }
        __syncthreads();   // S5

        // ---- Phase D: tape update + hwork <- hnew (both batches) ----
#pragma unroll
        for (int g = 0; g < 2; g++) {
#pragma unroll
            for (int e = 0; e < NTAPE * RPC; e += NTHREADS) {
                int idx = e + t;
                int n = idx >> 5, dl = idx & 31;
                float a  = S.attn[g][n];
                float tp = S.tape[g][n * 33 + dl];
                S.tape[g][n * 33 + dl] = tp - tp * a + S.wv[g][dl] * a;
            }
            S.hwork[g][t]       = S.hnew[g][t];
            S.hwork[g][t + 256] = S.hnew[g][t + 256];
        }
        __syncthreads();   // S6
    }

    // ---- final tape output (both batches) ----
#pragma unroll
    for (int g = 0; g < 2; g++) {
        int bg = 2 * u + g;
        for (int e = t; e < NTAPE * RPC; e += NTHREADS) {
            int n = e >> 5, dl = e & 31;
            out[(size_t)BB * TT * DD + (size_t)(bg * NTAPE + n) * DD + d0 + dl] =
                S.tape[g][n * 33 + dl];
        }
    }
    CLUSTER_SYNC_();
}

// ---------------- fallback scan kernel (global-memory barriers) -----------
struct ScanSmem {
    float Wh[RPC * 512];
    float Ww[RPC * 512];
    float tape[NTAPE * 33];
    float hwork[512];
    float hnew[512];
    float acc[RPC];
    float wv[RPC];
    float rv[RPC];
    float attn[NTAPE];
    float score[NTAPE];
    float bh[RPC], gz[RPC], gr[RPC], gh[RPC], bg[RPC];
};

__device__ __forceinline__ void softmax64f(const float* __restrict__ score,
                                           float* __restrict__ attn, int t)
{
    if (t < 32) {
        float a = score[t], b = score[t + 32];
        float m = fmaxf(a, b);
#pragma unroll
        for (int off = 16; off >= 1; off >>= 1)
            m = fmaxf(m, __shfl_xor_sync(0xffffffffu, m, off));
        float e0 = __expf(a - m), e1 = __expf(b - m);
        float ss = e0 + e1;
#pragma unroll
        for (int off = 16; off >= 1; off >>= 1)
            ss += __shfl_xor_sync(0xffffffffu, ss, off);
        float inv = 1.f / ss;
        attn[t] = e0 * inv;
        attn[t + 32] = e1 * inv;
    }
}

__global__ __launch_bounds__(NTHREADS, 1) void scan_kernel(
    const float* __restrict__ tape_init,
    const float* __restrict__ hwork_init,
    const float* __restrict__ W_h,
    const float* __restrict__ b_h,
    const float* __restrict__ W_write,
    const float* __restrict__ gzv,
    const float* __restrict__ grv,
    const float* __restrict__ ghv,
    const float* __restrict__ bgv,
    float* __restrict__ out)
{
    extern __shared__ char raw[];
    ScanSmem& S = *(ScanSmem*)raw;

    const int t  = threadIdx.x;
    const int b  = blockIdx.x / CPB;
    const int c  = blockIdx.x % CPB;
    const int d0 = c * RPC;
    const float scale = 0.044194173824159216f;

    for (int i = t; i < RPC * 512; i += NTHREADS) {
        S.Wh[i] = W_h[(size_t)d0 * 512 + i];
        S.Ww[i] = W_write[(size_t)d0 * 512 + i];
    }
    for (int i = t; i < NTAPE * RPC; i += NTHREADS) {
        int n = i >> 5, dl = i & 31;
        S.tape[n * 33 + dl] = tape_init[(size_t)(b * NTAPE + n) * DD + d0 + dl];
    }
    for (int i = t; i < 512; i += NTHREADS)
        S.hwork[i] = hwork_init[b * 512 + i];
    if (t < RPC) {
        S.bh[t] = b_h[d0 + t];  S.gz[t] = gzv[d0 + t];
        S.gr[t] = grv[d0 + t];  S.gh[t] = ghv[d0 + t];
        S.bg[t] = bgv[d0 + t];
    }
    __syncthreads();

    unsigned bc = 0;
    const int n4 = t >> 2, q4 = t & 3;
    const int dl8 = t >> 3, q8 = t & 7;

    for (int step = 0; step < TT; step++) {
        {
            float s = 0.f;
#pragma unroll
            for (int k = 0; k < 8; k++) {
                int dl = q4 * 8 + k;
                s += S.hwork[d0 + dl] * S.tape[n4 * 33 + dl];
            }
            s += __shfl_down_sync(0xffffffffu, s, 2);
            s += __shfl_down_sync(0xffffffffu, s, 1);
            if (q4 == 0) g_rs[(b * CPB + c) * NTAPE + n4] = s;
        }
        matvec32(S.Wh, S.hwork, S.acc);
        batch_barrier(b, (++bc) * CPB);

        if (t < NTAPE) {
            float s = 0.f;
#pragma unroll
            for (int cc = 0; cc < CPB; cc++)
                s += __ldcg(&g_rs[(b * CPB + cc) * NTAPE + t]);
            S.score[t] = s * scale;
        }
        __syncthreads();
        softmax64f(S.score, S.attn, t);
        __syncthreads();
        {
            float s = 0.f;
#pragma unroll
            for (int k = 0; k < 8; k++) {
                int n = q8 * 8 + k;
                s += S.attn[n] * S.tape[n * 33 + dl8];
            }
            s += __shfl_down_sync(0xffffffffu, s, 4);
            s += __shfl_down_sync(0xffffffffu, s, 2);
            s += __shfl_down_sync(0xffffffffu, s, 1);
            if (q8 == 0) S.rv[dl8] = s;
        }
        __syncthreads();
        if (t < RPC) {
            size_t row = (size_t)(b * TT + step) * EE;
            float xp = g_xz[row + d0 + t];
            float zt = g_xz[row + 512 + d0 + t];
            float hn = tanhf(xp + S.acc[t] + S.rv[t] + S.bh[t]);
            g_hnew[b * 512 + d0 + t] = hn;
            float gi = zt * S.gz[t] + S.rv[t] * S.gr[t] + hn * S.gh[t] + S.bg[t];
            gi = fminf(fmaxf(gi, -20.f), 20.f);
            float sig = 1.f / (1.f + __expf(-gi));
            out[(size_t)(b * TT + step) * DD + d0 + t] = hn * gi * sig;
        }
        batch_barrier(b, (++bc) * CPB);

        S.hnew[t]       = __ldcg(&g_hnew[b * 512 + t]);
        S.hnew[t + 256] = __ldcg(&g_hnew[b * 512 + t + 256]);
        __syncthreads();
        matvec32(S.Ww, S.hnew, S.wv);
        __syncthreads();
        {
            float s = 0.f;
#pragma unroll
            for (int k = 0; k < 8; k++) {
                int dl = q4 * 8 + k;
                s += S.wv[dl] * S.tape[n4 * 33 + dl];
            }
            s += __shfl_down_sync(0xffffffffu, s, 2);
            s += __shfl_down_sync(0xffffffffu, s, 1);
            if (q4 == 0) g_ws[(b * CPB + c) * NTAPE + n4] = s;
        }
        batch_barrier(b, (++bc) * CPB);

        if (t < NTAPE) {
            float s = 0.f;
#pragma unroll
            for (int cc = 0; cc < CPB; cc++)
                s += __ldcg(&g_ws[(b * CPB + cc) * NTAPE + t]);
            S.score[t] = s * scale;
        }
        __syncthreads();
        softmax64f(S.score, S.attn, t);
        __syncthreads();
        for (int e = t; e < NTAPE * RPC; e += NTHREADS) {
            int n = e >> 5, dl = e & 31;
            float a  = S.attn[n];
            float tp = S.tape[n * 33 + dl];
            S.tape[n * 33 + dl] = tp - tp * a + S.wv[dl] * a;
        }
        S.hwork[t]       = S.hnew[t];
        S.hwork[t + 256] = S.hnew[t + 256];
        __syncthreads();
    }

    for (int e = t; e < NTAPE * RPC; e += NTHREADS) {
        int n = e >> 5, dl = e & 31;
        out[(size_t)BB * TT * DD + (size_t)(b * NTAPE + n) * DD + d0 + dl] =
            S.tape[n * 33 + dl];
    }
}

// ---------------- launch ---------------------------------------------------
extern "C" void kernel_launch(void* const* d_in, const int* in_sizes, int n_in,
                              void* d_out, int out_size)
{
    const float* x         = (const float*)d_in[0];
    const float* tape_init = (const float*)d_in[1];
    const float* hwork     = (const float*)d_in[2];
    const float* W_h       = (const float*)d_in[3];
    const float* W_xz      = (const float*)d_in[4];
    const float* b_h       = (const float*)d_in[5];
    const float* W_write   = (const float*)d_in[6];
    const float* g_z       = (const float*)d_in[7];
    const float* g_r       = (const float*)d_in[8];
    const float* g_h       = (const float*)d_in[9];
    const float* b_gate    = (const float*)d_in[10];
    float* out = (float*)d_out;

    gemm_xz_kernel<<<dim3(EE / 64, (BB * TT) / 64), 256>>>(x, W_xz);

    // ---- primary: dual-batch 16-CTA-cluster scan ----
    cudaFuncSetAttribute(scan2_kernel,
                         cudaFuncAttributeMaxDynamicSharedMemorySize,
                         (int)sizeof(CS));
    cudaError_t aerr = cudaFuncSetAttribute(
        scan2_kernel, cudaFuncAttributeNonPortableClusterSizeAllowed, 1);

    cudaLaunchConfig_t cfg = {};
    cfg.gridDim  = dim3(NCLU * CPB, 1, 1);
    cfg.blockDim = dim3(NTHREADS, 1, 1);
    cfg.dynamicSmemBytes = sizeof(CS);
    cfg.stream = 0;

    int maxClu = 0;
    cudaError_t qerr = cudaOccupancyMaxPotentialClusterSize(
        &maxClu, scan2_kernel, &cfg);

    bool launched = false;
    if (aerr == cudaSuccess && qerr == cudaSuccess && maxClu >= CPB) {
        cudaLaunchAttribute attrs[1];
        attrs[0].id = cudaLaunchAttributeClusterDimension;
        attrs[0].val.clusterDim.x = CPB;
        attrs[0].val.clusterDim.y = 1;
        attrs[0].val.clusterDim.z = 1;
        cfg.attrs = attrs;
        cfg.numAttrs = 1;
        cudaError_t lerr = cudaLaunchKernelEx(&cfg, scan2_kernel,
            tape_init, hwork, W_h, b_h, W_write, g_z, g_r, g_h, b_gate, out);
        launched = (lerr == cudaSuccess);
    }

    // ---- fallback ----
    if (!launched) {
        cudaFuncSetAttribute(scan_kernel,
                             cudaFuncAttributeMaxDynamicSharedMemorySize,
                             (int)sizeof(ScanSmem));
        init_bar_kernel<<<1, 32>>>();
        scan_kernel<<<BB * CPB, NTHREADS, sizeof(ScanSmem)>>>(
            tape_init, hwork, W_h, b_h, W_write, g_z, g_r, g_h, b_gate, out);
    }
}

// round 5
// speedup vs baseline: 2.3549x; 1.5347x over previous
#include <cuda_runtime.h>
#include <cstdint>
#include <cstddef>

// Problem constants
#define BB   8
#define TT   1024
#define DD   512
#define EE   1024
#define NTAPE 64
#define CPB  16        // CTAs per cluster
#define RPC  32        // rows / tape-cols per CTA
#define NTHREADS 256
#define NCLU  4        // clusters (2 batches each)

// ---------------- device scratch ----------
__device__ float    g_xz[(size_t)BB * TT * EE];
__device__ float    g_rs[BB * CPB * NTAPE];         // fallback exchange
__device__ float    g_ws[BB * CPB * NTAPE];
__device__ float    g_hnew[BB * DD];
__device__ unsigned g_bar[BB];

__global__ void init_bar_kernel() {
    if (threadIdx.x < BB) g_bar[threadIdx.x] = 0u;
}

// ---------------- projection GEMM ----------
__global__ __launch_bounds__(256) void gemm_xz_kernel(
    const float* __restrict__ X, const float* __restrict__ W)
{
    __shared__ float As[16][68];
    __shared__ float Bs[16][68];
    const int m0 = blockIdx.y * 64;
    const int e0 = blockIdx.x * 64;
    const int tid = threadIdx.x;
    const int tx = tid & 15;
    const int ty = tid >> 4;
    const int lr = tid >> 2;
    const int lc = (tid & 3) * 4;
    float acc[4][4] = {};
    for (int kt = 0; kt < 512; kt += 16) {
        float4 xv = *(const float4*)(X + (size_t)(m0 + lr) * 512 + kt + lc);
        float4 wv = *(const float4*)(W + (size_t)(e0 + lr) * 512 + kt + lc);
        __syncthreads();
        As[lc + 0][lr] = xv.x; As[lc + 1][lr] = xv.y;
        As[lc + 2][lr] = xv.z; As[lc + 3][lr] = xv.w;
        Bs[lc + 0][lr] = wv.x; Bs[lc + 1][lr] = wv.y;
        Bs[lc + 2][lr] = wv.z; Bs[lc + 3][lr] = wv.w;
        __syncthreads();
#pragma unroll
        for (int kk = 0; kk < 16; kk++) {
            float4 a  = *(const float4*)&As[kk][ty * 4];
            float4 bv = *(const float4*)&Bs[kk][tx * 4];
            float av[4] = {a.x, a.y, a.z, a.w};
            float bw[4] = {bv.x, bv.y, bv.z, bv.w};
#pragma unroll
            for (int i = 0; i < 4; i++)
#pragma unroll
                for (int j = 0; j < 4; j++)
                    acc[i][j] += av[i] * bw[j];
        }
    }
#pragma unroll
    for (int i = 0; i < 4; i++) {
        float4 o = make_float4(acc[i][0], acc[i][1], acc[i][2], acc[i][3]);
        *(float4*)(&g_xz[(size_t)(m0 + ty * 4 + i) * EE + e0 + tx * 4]) = o;
    }
}

// ---------------- helpers ------------------------------------------
__device__ __forceinline__ uint32_t smem_u32(const void* p) {
    return (uint32_t)__cvta_generic_to_shared(p);
}
__device__ __forceinline__ uint32_t mapa_u32(uint32_t local_addr, uint32_t rank) {
    uint32_t r;
    asm volatile("mapa.shared::cluster.u32 %0, %1, %2;"
                 : "=r"(r) : "r"(local_addr), "r"(rank));
    return r;
}
#define CLUSTER_SYNC_() do {                                              \
    asm volatile("barrier.cluster.arrive.aligned;" ::: "memory");         \
    asm volatile("barrier.cluster.wait.aligned;"   ::: "memory");         \
} while (0)

__device__ __forceinline__ void push_async(uint32_t raddr, float v, uint32_t rmbar) {
    asm volatile(
        "st.async.shared::cluster.mbarrier::complete_tx::bytes.b32 [%0], %1, [%2];"
        :: "r"(raddr), "r"(__float_as_uint(v)), "r"(rmbar) : "memory");
}
__device__ __forceinline__ void mbar_init(uint32_t mbar, uint32_t cnt) {
    asm volatile("mbarrier.init.shared.b64 [%0], %1;" :: "r"(mbar), "r"(cnt) : "memory");
}
__device__ __forceinline__ void mbar_expect_tx(uint32_t mbar, uint32_t bytes) {
    asm volatile("mbarrier.arrive.expect_tx.shared.b64 _, [%0], %1;"
                 :: "r"(mbar), "r"(bytes) : "memory");
}
__device__ __forceinline__ void mbar_wait_cta(uint32_t mbar, uint32_t parity) {
    asm volatile(
        "{\n\t"
        ".reg .pred P1;\n\t"
        "WAIT_LOOP_%=:\n\t"
        "mbarrier.try_wait.parity.acquire.cta.shared::cta.b64 P1, [%0], %1, 0x989680;\n\t"
        "@P1 bra.uni WAIT_DONE_%=;\n\t"
        "bra.uni WAIT_LOOP_%=;\n\t"
        "WAIT_DONE_%=:\n\t"
        "}"
        :: "r"(mbar), "r"(parity) : "memory");
}

// packed f32x2 fma: d = a*b + d (elementwise on 2 floats)
__device__ __forceinline__ void fma2(unsigned long long& d,
                                     unsigned long long a,
                                     unsigned long long b) {
    asm("fma.rn.f32x2 %0, %1, %2, %0;" : "+l"(d) : "l"(a), "l"(b));
}
union UF2 { unsigned long long u; float2 f; };

__device__ __forceinline__ unsigned ld_acq_u32(const unsigned* p) {
    unsigned v;
    asm volatile("ld.global.acquire.gpu.u32 %0, [%1];" : "=r"(v) : "l"(p));
    return v;
}
__device__ __forceinline__ void batch_barrier(int b, unsigned target) {
    __syncthreads();
    if (threadIdx.x == 0) {
        __threadfence();
        atomicAdd(&g_bar[b], 1u);
        while (ld_acq_u32(&g_bar[b]) < target) { }
    }
    __syncthreads();
}

// (fallback-only) conflict-free smem matvec
__device__ __forceinline__ void matvec32(const float* __restrict__ sW,
                                         const float* __restrict__ vec,
                                         float* __restrict__ dest)
{
    const int lane = threadIdx.x & 31;
    const int warp = threadIdx.x >> 5;
    float4 v0 = *(const float4*)(vec + 0   + lane * 4);
    float4 v1 = *(const float4*)(vec + 128 + lane * 4);
    float4 v2 = *(const float4*)(vec + 256 + lane * 4);
    float4 v3 = *(const float4*)(vec + 384 + lane * 4);
#pragma unroll
    for (int rr = 0; rr < 4; rr++) {
        int r = warp * 4 + rr;
        const float* w = sW + r * 512;
        float4 w0 = *(const float4*)(w + 0   + lane * 4);
        float4 w1 = *(const float4*)(w + 128 + lane * 4);
        float4 w2 = *(const float4*)(w + 256 + lane * 4);
        float4 w3 = *(const float4*)(w + 384 + lane * 4);
        float s = w0.x * v0.x + w0.y * v0.y + w0.z * v0.z + w0.w * v0.w
                + w1.x * v1.x + w1.y * v1.y + w1.z * v1.z + w1.w * v1.w
                + w2.x * v2.x + w2.y * v2.y + w2.z * v2.z + w2.w * v2.w
                + w3.x * v3.x + w3.y * v3.y + w3.z * v3.z + w3.w * v3.w;
#pragma unroll
        for (int off = 16; off >= 1; off >>= 1)
            s += __shfl_down_sync(0xffffffffu, s, off);
        if (lane == 0) dest[r] = s;
    }
}

// ---------------- dual-batch cluster scan: weights in registers -----------
struct __align__(16) CS {
    float tape[2][NTAPE * 33];    // 16.9 KB
    float hnew[2][512];           // doubles as h_work (local slice reads only)
    float rs[2][CPB * NTAPE];
    float ws[2][CPB * NTAPE];
    float acc[2][RPC];            // Wh @ h  (for next step's h_new)
    float wv[2][RPC];             // Ww @ h
    float attn[2][NTAPE];
    float bh[RPC], gz[RPC], gr[RPC], gh[RPC], bg[RPC];
    unsigned long long mb_rs[2], mb_hn[2], mb_ws[2];
};

#define RS_BYTES ((CPB - 1) * NTAPE * 4)   // 3840
#define HN_BYTES ((CPB - 1) * RPC * 4)     // 1920
#define WS_BYTES ((CPB - 1) * NTAPE * 4)

__global__ __launch_bounds__(NTHREADS, 1) void scan2_kernel(
    const float* __restrict__ tape_init,
    const float* __restrict__ hwork_init,
    const float* __restrict__ W_h,
    const float* __restrict__ b_h,
    const float* __restrict__ W_write,
    const float* __restrict__ gzv,
    const float* __restrict__ grv,
    const float* __restrict__ ghv,
    const float* __restrict__ bgv,
    float* __restrict__ out)
{
    extern __shared__ char raw[];
    CS& S = *(CS*)raw;

    const int t    = threadIdx.x;
    const int lane = t & 31;
    const int cw   = t >> 5;
    const int u    = blockIdx.x >> 4;     // cluster index (batch pair)
    const int c    = blockIdx.x & 15;     // cluster rank
    const int d0   = c * RPC;
    const float scale = 0.044194173824159216f;  // 1/sqrt(512)

    const bool isctrl = (cw == 0) || (cw == 5);
    const int  gme    = (cw == 5) ? 1 : 0;

    // ---- weights into registers: warp cw owns rows cw*4..cw*4+3 ----
    // lane holds cols {ch*128 + lane*4 .. +3} for ch=0..3, as 8 f32x2 per row.
    unsigned long long wh[4][8], ww[4][8];
#pragma unroll
    for (int i = 0; i < 4; i++) {
        const size_t rowoff = (size_t)(d0 + cw * 4 + i) * 512;
#pragma unroll
        for (int ch = 0; ch < 4; ch++) {
            ulonglong2 a = *(const ulonglong2*)(W_h     + rowoff + ch * 128 + lane * 4);
            ulonglong2 b = *(const ulonglong2*)(W_write + rowoff + ch * 128 + lane * 4);
            wh[i][ch * 2] = a.x; wh[i][ch * 2 + 1] = a.y;
            ww[i][ch * 2] = b.x; ww[i][ch * 2 + 1] = b.y;
        }
    }

    // ---- one-time smem loads ----
#pragma unroll
    for (int g = 0; g < 2; g++) {
        int bg = 2 * u + g;
        for (int i = t; i < NTAPE * RPC; i += NTHREADS) {
            int n = i >> 5, dl = i & 31;
            S.tape[g][n * 33 + dl] = tape_init[(size_t)(bg * NTAPE + n) * DD + d0 + dl];
        }
        for (int i = t; i < 512; i += NTHREADS)
            S.hnew[g][i] = hwork_init[bg * 512 + i];
    }
    if (t < RPC) {
        S.bh[t] = b_h[d0 + t];  S.gz[t] = gzv[d0 + t];
        S.gr[t] = grv[d0 + t];  S.gh[t] = ghv[d0 + t];
        S.bg[t] = bgv[d0 + t];
    }

    const uint32_t sbase = smem_u32(&S);
    uint32_t pb[CPB];
#pragma unroll
    for (int r = 0; r < CPB; r++) pb[r] = mapa_u32(sbase, r);

    uint32_t mbrs[2], mbhn[2], mbws[2];
    uint32_t off_rs[2], off_hn[2], off_ws[2];
    uint32_t off_mbrs[2], off_mbhn[2], off_mbws[2];
#pragma unroll
    for (int g = 0; g < 2; g++) {
        mbrs[g] = smem_u32(&S.mb_rs[g]);
        mbhn[g] = smem_u32(&S.mb_hn[g]);
        mbws[g] = smem_u32(&S.mb_ws[g]);
        off_rs[g] = smem_u32(&S.rs[g][0]) - sbase;
        off_hn[g] = smem_u32(&S.hnew[g][0]) - sbase;
        off_ws[g] = smem_u32(&S.ws[g][0]) - sbase;
        off_mbrs[g] = mbrs[g] - sbase;
        off_mbhn[g] = mbhn[g] - sbase;
        off_mbws[g] = mbws[g] - sbase;
    }
    if (t == 0) {
#pragma unroll
        for (int g = 0; g < 2; g++) {
            mbar_init(mbrs[g], 1); mbar_init(mbhn[g], 1); mbar_init(mbws[g], 1);
            mbar_expect_tx(mbrs[g], RS_BYTES);
            mbar_expect_tx(mbhn[g], HN_BYTES);
            mbar_expect_tx(mbws[g], WS_BYTES);
        }
    }
    __syncthreads();

    // ---- pre-loop: acc[g] = Wh @ h_init (register matvec) ----
#pragma unroll
    for (int g = 0; g < 2; g++) {
        unsigned long long v[8];
#pragma unroll
        for (int ch = 0; ch < 4; ch++) {
            ulonglong2 tv = *(const ulonglong2*)(&S.hnew[g][ch * 128 + lane * 4]);
            v[ch * 2] = tv.x; v[ch * 2 + 1] = tv.y;
        }
        unsigned long long a2[4] = {0ull, 0ull, 0ull, 0ull};
#pragma unroll
        for (int i = 0; i < 4; i++)
#pragma unroll
            for (int p = 0; p < 8; p++) fma2(a2[i], wh[i][p], v[p]);
        float sa[4];
#pragma unroll
        for (int i = 0; i < 4; i++) { UF2 x; x.u = a2[i]; sa[i] = x.f.x + x.f.y; }
#pragma unroll
        for (int off = 16; off >= 1; off >>= 1) {
#pragma unroll
            for (int i = 0; i < 4; i++)
                sa[i] += __shfl_xor_sync(0xffffffffu, sa[i], off);
        }
        if (lane == 0)
            *(float4*)&S.acc[g][cw * 4] = make_float4(sa[0], sa[1], sa[2], sa[3]);
    }
    __syncthreads();
    CLUSTER_SYNC_();

    const int n4 = t >> 2, q4 = t & 3;

    for (int step = 0; step < TT; step++) {
        const uint32_t par = step & 1u;

        // ---- prefetch xz (ctrl warps) ----
        float xp = 0.f, zt = 0.f;
        if (isctrl) {
            size_t row = (size_t)((2 * u + gme) * TT + step) * EE;
            xp = __ldcs(&g_xz[row + d0 + lane]);
            zt = __ldcs(&g_xz[row + 512 + d0 + lane]);
        }

        // ---- Phase A: read-score partials (h local slice in S.hnew) ----
#pragma unroll
        for (int g = 0; g < 2; g++) {
            float s = 0.f;
#pragma unroll
            for (int k = 0; k < 8; k++) {
                int dl = q4 * 8 + k;
                s += S.hnew[g][d0 + dl] * S.tape[g][n4 * 33 + dl];
            }
            s += __shfl_down_sync(0xffffffffu, s, 2);
            s += __shfl_down_sync(0xffffffffu, s, 1);
            if (q4 == 0) {
                S.rs[g][c * NTAPE + n4] = s;
                uint32_t doff = off_rs[g] + (uint32_t)(c * NTAPE + n4) * 4;
#pragma unroll
                for (int r = 0; r < CPB; r++) {
                    if (r == c) continue;
                    push_async(pb[r] + doff, s, pb[r] + off_mbrs[g]);
                }
            }
        }
        __syncthreads();   // S1

        // ---- Phase B (ctrl warps): softmax, read_val, h_new, out ----
        if (isctrl) {
            const int g = gme;
            const int bg = 2 * u + g;
            mbar_wait_cta(mbrs[g], par);
            if (lane == 0) mbar_expect_tx(mbrs[g], RS_BYTES);
            float a0 = 0.f, a1 = 0.f, a2s = 0.f, a3s = 0.f;
#pragma unroll
            for (int cc = 0; cc < CPB; cc += 2) {
                a0  += S.rs[g][cc * NTAPE + lane];
                a1  += S.rs[g][cc * NTAPE + lane + 32];
                a2s += S.rs[g][(cc + 1) * NTAPE + lane];
                a3s += S.rs[g][(cc + 1) * NTAPE + lane + 32];
            }
            a0 = (a0 + a2s) * scale; a1 = (a1 + a3s) * scale;
            float m = fmaxf(a0, a1);
#pragma unroll
            for (int off = 16; off >= 1; off >>= 1)
                m = fmaxf(m, __shfl_xor_sync(0xffffffffu, m, off));
            float e0 = __expf(a0 - m), e1 = __expf(a1 - m);
            float ss = e0 + e1;
#pragma unroll
            for (int off = 16; off >= 1; off >>= 1)
                ss += __shfl_xor_sync(0xffffffffu, ss, off);
            float inv = 1.f / ss;
            e0 *= inv; e1 *= inv;
            // read_val with 4 independent chains
            float rv0 = 0.f, rv1 = 0.f, rv2 = 0.f, rv3 = 0.f;
#pragma unroll
            for (int k = 0; k < 8; k++) {
                rv0 += __shfl_sync(0xffffffffu, e0, 4 * k + 0) * S.tape[g][(4 * k + 0) * 33 + lane];
                rv1 += __shfl_sync(0xffffffffu, e0, 4 * k + 1) * S.tape[g][(4 * k + 1) * 33 + lane];
                rv2 += __shfl_sync(0xffffffffu, e0, 4 * k + 2) * S.tape[g][(4 * k + 2) * 33 + lane];
                rv3 += __shfl_sync(0xffffffffu, e0, 4 * k + 3) * S.tape[g][(4 * k + 3) * 33 + lane];
            }
#pragma unroll
            for (int k = 0; k < 8; k++) {
                rv0 += __shfl_sync(0xffffffffu, e1, 4 * k + 0) * S.tape[g][(32 + 4 * k + 0) * 33 + lane];
                rv1 += __shfl_sync(0xffffffffu, e1, 4 * k + 1) * S.tape[g][(32 + 4 * k + 1) * 33 + lane];
                rv2 += __shfl_sync(0xffffffffu, e1, 4 * k + 2) * S.tape[g][(32 + 4 * k + 2) * 33 + lane];
                rv3 += __shfl_sync(0xffffffffu, e1, 4 * k + 3) * S.tape[g][(32 + 4 * k + 3) * 33 + lane];
            }
            float rv = (rv0 + rv1) + (rv2 + rv3);
            float pre = xp + S.acc[g][lane] + rv + S.bh[lane];
            float ex2 = __expf(2.f * pre);
            float hn  = 1.f - 2.f / (ex2 + 1.f);
            S.hnew[g][d0 + lane] = hn;
            uint32_t doff = off_hn[g] + (uint32_t)(d0 + lane) * 4;
#pragma unroll
            for (int r = 0; r < CPB; r++) {
                if (r == c) continue;
                push_async(pb[r] + doff, hn, pb[r] + off_mbhn[g]);
            }
            float gi = zt * S.gz[lane] + rv * S.gr[lane] + hn * S.gh[lane] + S.bg[lane];
            gi = fminf(fmaxf(gi, -20.f), 20.f);
            float sig = 1.f / (1.f + __expf(-gi));
            out[(size_t)(bg * TT + step) * DD + d0 + lane] = hn * gi * sig;
            mbar_wait_cta(mbhn[g], par);
            if (lane == 0) mbar_expect_tx(mbhn[g], HN_BYTES);
        }
        __syncthreads();   // S2

        // ---- Phase C: dual register matvec on full h_new (both batches) ----
#pragma unroll
        for (int g = 0; g < 2; g++) {
            unsigned long long v[8];
#pragma unroll
            for (int ch = 0; ch < 4; ch++) {
                ulonglong2 tv = *(const ulonglong2*)(&S.hnew[g][ch * 128 + lane * 4]);
                v[ch * 2] = tv.x; v[ch * 2 + 1] = tv.y;
            }
            unsigned long long a2[4] = {0ull, 0ull, 0ull, 0ull};
            unsigned long long b2[4] = {0ull, 0ull, 0ull, 0ull};
#pragma unroll
            for (int i = 0; i < 4; i++)
#pragma unroll
                for (int p = 0; p < 8; p++) {
                    fma2(a2[i], wh[i][p], v[p]);
                    fma2(b2[i], ww[i][p], v[p]);
                }
            float sa[4], sb[4];
#pragma unroll
            for (int i = 0; i < 4; i++) {
                UF2 x; x.u = a2[i]; sa[i] = x.f.x + x.f.y;
                UF2 y; y.u = b2[i]; sb[i] = y.f.x + y.f.y;
            }
#pragma unroll
            for (int off = 16; off >= 1; off >>= 1) {
#pragma unroll
                for (int i = 0; i < 4; i++) {
                    sa[i] += __shfl_xor_sync(0xffffffffu, sa[i], off);
                    sb[i] += __shfl_xor_sync(0xffffffffu, sb[i], off);
                }
            }
            if (lane == 0) {
                *(float4*)&S.acc[g][cw * 4] = make_float4(sa[0], sa[1], sa[2], sa[3]);
                *(float4*)&S.wv[g][cw * 4]  = make_float4(sb[0], sb[1], sb[2], sb[3]);
            }
        }
        __syncthreads();   // S3

        // ---- write-score partials (both batches) ----
#pragma unroll
        for (int g = 0; g < 2; g++) {
            float s = 0.f;
#pragma unroll
            for (int k = 0; k < 8; k++) {
                int dl = q4 * 8 + k;
                s += S.wv[g][dl] * S.tape[g][n4 * 33 + dl];
            }
            s += __shfl_down_sync(0xffffffffu, s, 2);
            s += __shfl_down_sync(0xffffffffu, s, 1);
            if (q4 == 0) {
                S.ws[g][c * NTAPE + n4] = s;
                uint32_t doff = off_ws[g] + (uint32_t)(c * NTAPE + n4) * 4;
#pragma unroll
                for (int r = 0; r < CPB; r++) {
                    if (r == c) continue;
                    push_async(pb[r] + doff, s, pb[r] + off_mbws[g]);
                }
            }
        }
        __syncthreads();   // S4

        // ---- write softmax (ctrl warps) ----
        if (isctrl) {
            const int g = gme;
            mbar_wait_cta(mbws[g], par);
            if (lane == 0) mbar_expect_tx(mbws[g], WS_BYTES);
            float a0 = 0.f, a1 = 0.f, a2s = 0.f, a3s = 0.f;
#pragma unroll
            for (int cc = 0; cc < CPB; cc += 2) {
                a0  += S.ws[g][cc * NTAPE + lane];
                a1  += S.ws[g][cc * NTAPE + lane + 32];
                a2s += S.ws[g][(cc + 1) * NTAPE + lane];
                a3s += S.ws[g][(cc + 1) * NTAPE + lane + 32];
            }
            a0 = (a0 + a2s) * scale; a1 = (a1 + a3s) * scale;
            float m = fmaxf(a0, a1);
#pragma unroll
            for (int off = 16; off >= 1; off >>= 1)
                m = fmaxf(m, __shfl_xor_sync(0xffffffffu, m, off));
            float e0 = __expf(a0 - m), e1 = __expf(a1 - m);
            float ss = e0 + e1;
#pragma unroll
            for (int off = 16; off >= 1; off >>= 1)
                ss += __shfl_xor_sync(0xffffffffu, ss, off);
            float inv = 1.f / ss;
            S.attn[g][lane]      = e0 * inv;
            S.attn[g][lane + 32] = e1 * inv;
        }
        __syncthreads();   // S5

        // ---- Phase D: tape update (both batches) ----
#pragma unroll
        for (int g = 0; g < 2; g++) {
#pragma unroll
            for (int e = 0; e < NTAPE * RPC; e += NTHREADS) {
                int idx = e + t;
                int n = idx >> 5, dl = idx & 31;
                float a  = S.attn[g][n];
                float tp = S.tape[g][n * 33 + dl];
                S.tape[g][n * 33 + dl] = tp - tp * a + S.wv[g][dl] * a;
            }
        }
        __syncthreads();   // S6
    }

    // ---- final tape output ----
#pragma unroll
    for (int g = 0; g < 2; g++) {
        int bg = 2 * u + g;
        for (int e = t; e < NTAPE * RPC; e += NTHREADS) {
            int n = e >> 5, dl = e & 31;
            out[(size_t)BB * TT * DD + (size_t)(bg * NTAPE + n) * DD + d0 + dl] =
                S.tape[g][n * 33 + dl];
        }
    }
    CLUSTER_SYNC_();
}

// ---------------- fallback scan kernel (global-memory barriers) -----------
struct ScanSmem {
    float Wh[RPC * 512];
    float Ww[RPC * 512];
    float tape[NTAPE * 33];
    float hwork[512];
    float hnew[512];
    float acc[RPC];
    float wv[RPC];
    float rv[RPC];
    float attn[NTAPE];
    float score[NTAPE];
    float bh[RPC], gz[RPC], gr[RPC], gh[RPC], bg[RPC];
};

__device__ __forceinline__ void softmax64f(const float* __restrict__ score,
                                           float* __restrict__ attn, int t)
{
    if (t < 32) {
        float a = score[t], b = score[t + 32];
        float m = fmaxf(a, b);
#pragma unroll
        for (int off = 16; off >= 1; off >>= 1)
            m = fmaxf(m, __shfl_xor_sync(0xffffffffu, m, off));
        float e0 = __expf(a - m), e1 = __expf(b - m);
        float ss = e0 + e1;
#pragma unroll
        for (int off = 16; off >= 1; off >>= 1)
            ss += __shfl_xor_sync(0xffffffffu, ss, off);
        float inv = 1.f / ss;
        attn[t] = e0 * inv;
        attn[t + 32] = e1 * inv;
    }
}

__global__ __launch_bounds__(NTHREADS, 1) void scan_kernel(
    const float* __restrict__ tape_init,
    const float* __restrict__ hwork_init,
    const float* __restrict__ W_h,
    const float* __restrict__ b_h,
    const float* __restrict__ W_write,
    const float* __restrict__ gzv,
    const float* __restrict__ grv,
    const float* __restrict__ ghv,
    const float* __restrict__ bgv,
    float* __restrict__ out)
{
    extern __shared__ char raw[];
    ScanSmem& S = *(ScanSmem*)raw;

    const int t  = threadIdx.x;
    const int b  = blockIdx.x / CPB;
    const int c  = blockIdx.x % CPB;
    const int d0 = c * RPC;
    const float scale = 0.044194173824159216f;

    for (int i = t; i < RPC * 512; i += NTHREADS) {
        S.Wh[i] = W_h[(size_t)d0 * 512 + i];
        S.Ww[i] = W_write[(size_t)d0 * 512 + i];
    }
    for (int i = t; i < NTAPE * RPC; i += NTHREADS) {
        int n = i >> 5, dl = i & 31;
        S.tape[n * 33 + dl] = tape_init[(size_t)(b * NTAPE + n) * DD + d0 + dl];
    }
    for (int i = t; i < 512; i += NTHREADS)
        S.hwork[i] = hwork_init[b * 512 + i];
    if (t < RPC) {
        S.bh[t] = b_h[d0 + t];  S.gz[t] = gzv[d0 + t];
        S.gr[t] = grv[d0 + t];  S.gh[t] = ghv[d0 + t];
        S.bg[t] = bgv[d0 + t];
    }
    __syncthreads();

    unsigned bc = 0;
    const int n4 = t >> 2, q4 = t & 3;
    const int dl8 = t >> 3, q8 = t & 7;

    for (int step = 0; step < TT; step++) {
        {
            float s = 0.f;
#pragma unroll
            for (int k = 0; k < 8; k++) {
                int dl = q4 * 8 + k;
                s += S.hwork[d0 + dl] * S.tape[n4 * 33 + dl];
            }
            s += __shfl_down_sync(0xffffffffu, s, 2);
            s += __shfl_down_sync(0xffffffffu, s, 1);
            if (q4 == 0) g_rs[(b * CPB + c) * NTAPE + n4] = s;
        }
        matvec32(S.Wh, S.hwork, S.acc);
        batch_barrier(b, (++bc) * CPB);

        if (t < NTAPE) {
            float s = 0.f;
#pragma unroll
            for (int cc = 0; cc < CPB; cc++)
                s += __ldcg(&g_rs[(b * CPB + cc) * NTAPE + t]);
            S.score[t] = s * scale;
        }
        __syncthreads();
        softmax64f(S.score, S.attn, t);
        __syncthreads();
        {
            float s = 0.f;
#pragma unroll
            for (int k = 0; k < 8; k++) {
                int n = q8 * 8 + k;
                s += S.attn[n] * S.tape[n * 33 + dl8];
            }
            s += __shfl_down_sync(0xffffffffu, s, 4);
            s += __shfl_down_sync(0xffffffffu, s, 2);
            s += __shfl_down_sync(0xffffffffu, s, 1);
            if (q8 == 0) S.rv[dl8] = s;
        }
        __syncthreads();
        if (t < RPC) {
            size_t row = (size_t)(b * TT + step) * EE;
            float xp = g_xz[row + d0 + t];
            float zt = g_xz[row + 512 + d0 + t];
            float hn = tanhf(xp + S.acc[t] + S.rv[t] + S.bh[t]);
            g_hnew[b * 512 + d0 + t] = hn;
            float gi = zt * S.gz[t] + S.rv[t] * S.gr[t] + hn * S.gh[t] + S.bg[t];
            gi = fminf(fmaxf(gi, -20.f), 20.f);
            float sig = 1.f / (1.f + __expf(-gi));
            out[(size_t)(b * TT + step) * DD + d0 + t] = hn * gi * sig;
        }
        batch_barrier(b, (++bc) * CPB);

        S.hnew[t]       = __ldcg(&g_hnew[b * 512 + t]);
        S.hnew[t + 256] = __ldcg(&g_hnew[b * 512 + t + 256]);
        __syncthreads();
        matvec32(S.Ww, S.hnew, S.wv);
        __syncthreads();
        {
            float s = 0.f;
#pragma unroll
            for (int k = 0; k < 8; k++) {
                int dl = q4 * 8 + k;
                s += S.wv[dl] * S.tape[n4 * 33 + dl];
            }
            s += __shfl_down_sync(0xffffffffu, s, 2);
            s += __shfl_down_sync(0xffffffffu, s, 1);
            if (q4 == 0) g_ws[(b * CPB + c) * NTAPE + n4] = s;
        }
        batch_barrier(b, (++bc) * CPB);

        if (t < NTAPE) {
            float s = 0.f;
#pragma unroll
            for (int cc = 0; cc < CPB; cc++)
                s += __ldcg(&g_ws[(b * CPB + cc) * NTAPE + t]);
            S.score[t] = s * scale;
        }
        __syncthreads();
        softmax64f(S.score, S.attn, t);
        __syncthreads();
        for (int e = t; e < NTAPE * RPC; e += NTHREADS) {
            int n = e >> 5, dl = e & 31;
            float a  = S.attn[n];
            float tp = S.tape[n * 33 + dl];
            S.tape[n * 33 + dl] = tp - tp * a + S.wv[dl] * a;
        }
        S.hwork[t]       = S.hnew[t];
        S.hwork[t + 256] = S.hnew[t + 256];
        __syncthreads();
    }

    for (int e = t; e < NTAPE * RPC; e += NTHREADS) {
        int n = e >> 5, dl = e & 31;
        out[(size_t)BB * TT * DD + (size_t)(b * NTAPE + n) * DD + d0 + dl] =
            S.tape[n * 33 + dl];
    }
}

// ---------------- launch ---------------------------------------------------
extern "C" void kernel_launch(void* const* d_in, const int* in_sizes, int n_in,
                              void* d_out, int out_size)
{
    const float* x         = (const float*)d_in[0];
    const float* tape_init = (const float*)d_in[1];
    const float* hwork     = (const float*)d_in[2];
    const float* W_h       = (const float*)d_in[3];
    const float* W_xz      = (const float*)d_in[4];
    const float* b_h       = (const float*)d_in[5];
    const float* W_write   = (const float*)d_in[6];
    const float* g_z       = (const float*)d_in[7];
    const float* g_r       = (const float*)d_in[8];
    const float* g_h       = (const float*)d_in[9];
    const float* b_gate    = (const float*)d_in[10];
    float* out = (float*)d_out;

    gemm_xz_kernel<<<dim3(EE / 64, (BB * TT) / 64), 256>>>(x, W_xz);

    // ---- primary: dual-batch register-weight cluster scan ----
    cudaFuncSetAttribute(scan2_kernel,
                         cudaFuncAttributeMaxDynamicSharedMemorySize,
                         (int)sizeof(CS));
    cudaError_t aerr = cudaFuncSetAttribute(
        scan2_kernel, cudaFuncAttributeNonPortableClusterSizeAllowed, 1);

    cudaLaunchConfig_t cfg = {};
    cfg.gridDim  = dim3(NCLU * CPB, 1, 1);
    cfg.blockDim = dim3(NTHREADS, 1, 1);
    cfg.dynamicSmemBytes = sizeof(CS);
    cfg.stream = 0;

    int maxClu = 0;
    cudaError_t qerr = cudaOccupancyMaxPotentialClusterSize(
        &maxClu, scan2_kernel, &cfg);

    bool launched = false;
    if (aerr == cudaSuccess && qerr == cudaSuccess && maxClu >= CPB) {
        cudaLaunchAttribute attrs[1];
        attrs[0].id = cudaLaunchAttributeClusterDimension;
        attrs[0].val.clusterDim.x = CPB;
        attrs[0].val.clusterDim.y = 1;
        attrs[0].val.clusterDim.z = 1;
        cfg.attrs = attrs;
        cfg.numAttrs = 1;
        cudaError_t lerr = cudaLaunchKernelEx(&cfg, scan2_kernel,
            tape_init, hwork, W_h, b_h, W_write, g_z, g_r, g_h, b_gate, out);
        launched = (lerr == cudaSuccess);
    }

    // ---- fallback ----
    if (!launched) {
        cudaFuncSetAttribute(scan_kernel,
                             cudaFuncAttributeMaxDynamicSharedMemorySize,
                             (int)sizeof(ScanSmem));
        init_bar_kernel<<<1, 32>>>();
        scan_kernel<<<BB * CPB, NTHREADS, sizeof(ScanSmem)>>>(
            tape_init, hwork, W_h, b_h, W_write, g_z, g_r, g_h, b_gate, out);
    }
}

// round 6
// speedup vs baseline: 2.5411x; 1.0791x over previous
#include <cuda_runtime.h>
#include <cstdint>
#include <cstddef>

// Problem constants
#define BB   8
#define TT   1024
#define DD   512
#define EE   1024
#define NTAPE 64
#define CPB  16        // CTAs per cluster
#define RPC  32        // rows / tape-cols per CTA
#define NTHREADS 256
#define NCLU  4        // clusters (2 batches each)

// ---------------- device scratch ----------
__device__ float    g_xz[(size_t)BB * TT * EE];
__device__ float    g_rs[BB * CPB * NTAPE];         // fallback exchange
__device__ float    g_ws[BB * CPB * NTAPE];
__device__ float    g_hnew[BB * DD];
__device__ unsigned g_bar[BB];

__global__ void init_bar_kernel() {
    if (threadIdx.x < BB) g_bar[threadIdx.x] = 0u;
}

// ---------------- projection GEMM ----------
__global__ __launch_bounds__(256) void gemm_xz_kernel(
    const float* __restrict__ X, const float* __restrict__ W)
{
    __shared__ float As[16][68];
    __shared__ float Bs[16][68];
    const int m0 = blockIdx.y * 64;
    const int e0 = blockIdx.x * 64;
    const int tid = threadIdx.x;
    const int tx = tid & 15;
    const int ty = tid >> 4;
    const int lr = tid >> 2;
    const int lc = (tid & 3) * 4;
    float acc[4][4] = {};
    for (int kt = 0; kt < 512; kt += 16) {
        float4 xv = *(const float4*)(X + (size_t)(m0 + lr) * 512 + kt + lc);
        float4 wv = *(const float4*)(W + (size_t)(e0 + lr) * 512 + kt + lc);
        __syncthreads();
        As[lc + 0][lr] = xv.x; As[lc + 1][lr] = xv.y;
        As[lc + 2][lr] = xv.z; As[lc + 3][lr] = xv.w;
        Bs[lc + 0][lr] = wv.x; Bs[lc + 1][lr] = wv.y;
        Bs[lc + 2][lr] = wv.z; Bs[lc + 3][lr] = wv.w;
        __syncthreads();
#pragma unroll
        for (int kk = 0; kk < 16; kk++) {
            float4 a  = *(const float4*)&As[kk][ty * 4];
            float4 bv = *(const float4*)&Bs[kk][tx * 4];
            float av[4] = {a.x, a.y, a.z, a.w};
            float bw[4] = {bv.x, bv.y, bv.z, bv.w};
#pragma unroll
            for (int i = 0; i < 4; i++)
#pragma unroll
                for (int j = 0; j < 4; j++)
                    acc[i][j] += av[i] * bw[j];
        }
    }
#pragma unroll
    for (int i = 0; i < 4; i++) {
        float4 o = make_float4(acc[i][0], acc[i][1], acc[i][2], acc[i][3]);
        *(float4*)(&g_xz[(size_t)(m0 + ty * 4 + i) * EE + e0 + tx * 4]) = o;
    }
}

// ---------------- helpers ------------------------------------------
__device__ __forceinline__ uint32_t smem_u32(const void* p) {
    return (uint32_t)__cvta_generic_to_shared(p);
}
__device__ __forceinline__ uint32_t mapa_u32(uint32_t local_addr, uint32_t rank) {
    uint32_t r;
    asm volatile("mapa.shared::cluster.u32 %0, %1, %2;"
                 : "=r"(r) : "r"(local_addr), "r"(rank));
    return r;
}
#define CLUSTER_SYNC_() do {                                              \
    asm volatile("barrier.cluster.arrive.aligned;" ::: "memory");         \
    asm volatile("barrier.cluster.wait.aligned;"   ::: "memory");         \
} while (0)

__device__ __forceinline__ void push_async(uint32_t raddr, float v, uint32_t rmbar) {
    asm volatile(
        "st.async.shared::cluster.mbarrier::complete_tx::bytes.b32 [%0], %1, [%2];"
        :: "r"(raddr), "r"(__float_as_uint(v)), "r"(rmbar) : "memory");
}
__device__ __forceinline__ void mbar_init(uint32_t mbar, uint32_t cnt) {
    asm volatile("mbarrier.init.shared.b64 [%0], %1;" :: "r"(mbar), "r"(cnt) : "memory");
}
__device__ __forceinline__ void mbar_expect_tx(uint32_t mbar, uint32_t bytes) {
    asm volatile("mbarrier.arrive.expect_tx.shared.b64 _, [%0], %1;"
                 :: "r"(mbar), "r"(bytes) : "memory");
}
__device__ __forceinline__ void mbar_wait_cta(uint32_t mbar, uint32_t parity) {
    asm volatile(
        "{\n\t"
        ".reg .pred P1;\n\t"
        "WAIT_LOOP_%=:\n\t"
        "mbarrier.try_wait.parity.acquire.cta.shared::cta.b64 P1, [%0], %1, 0x989680;\n\t"
        "@P1 bra.uni WAIT_DONE_%=;\n\t"
        "bra.uni WAIT_LOOP_%=;\n\t"
        "WAIT_DONE_%=:\n\t"
        "}"
        :: "r"(mbar), "r"(parity) : "memory");
}

// packed f32x2 fma: d = a*b + d
__device__ __forceinline__ void fma2(unsigned long long& d,
                                     unsigned long long a,
                                     unsigned long long b) {
    asm("fma.rn.f32x2 %0, %1, %2, %0;" : "+l"(d) : "l"(a), "l"(b));
}
union UF2 { unsigned long long u; float2 f; };

__device__ __forceinline__ unsigned ld_acq_u32(const unsigned* p) {
    unsigned v;
    asm volatile("ld.global.acquire.gpu.u32 %0, [%1];" : "=r"(v) : "l"(p));
    return v;
}
__device__ __forceinline__ void batch_barrier(int b, unsigned target) {
    __syncthreads();
    if (threadIdx.x == 0) {
        __threadfence();
        atomicAdd(&g_bar[b], 1u);
        while (ld_acq_u32(&g_bar[b]) < target) { }
    }
    __syncthreads();
}

// (fallback-only) conflict-free smem matvec
__device__ __forceinline__ void matvec32(const float* __restrict__ sW,
                                         const float* __restrict__ vec,
                                         float* __restrict__ dest)
{
    const int lane = threadIdx.x & 31;
    const int warp = threadIdx.x >> 5;
    float4 v0 = *(const float4*)(vec + 0   + lane * 4);
    float4 v1 = *(const float4*)(vec + 128 + lane * 4);
    float4 v2 = *(const float4*)(vec + 256 + lane * 4);
    float4 v3 = *(const float4*)(vec + 384 + lane * 4);
#pragma unroll
    for (int rr = 0; rr < 4; rr++) {
        int r = warp * 4 + rr;
        const float* w = sW + r * 512;
        float4 w0 = *(const float4*)(w + 0   + lane * 4);
        float4 w1 = *(const float4*)(w + 128 + lane * 4);
        float4 w2 = *(const float4*)(w + 256 + lane * 4);
        float4 w3 = *(const float4*)(w + 384 + lane * 4);
        float s = w0.x * v0.x + w0.y * v0.y + w0.z * v0.z + w0.w * v0.w
                + w1.x * v1.x + w1.y * v1.y + w1.z * v1.z + w1.w * v1.w
                + w2.x * v2.x + w2.y * v2.y + w2.z * v2.z + w2.w * v2.w
                + w3.x * v3.x + w3.y * v3.y + w3.z * v3.z + w3.w * v3.w;
#pragma unroll
        for (int off = 16; off >= 1; off >>= 1)
            s += __shfl_down_sync(0xffffffffu, s, off);
        if (lane == 0) dest[r] = s;
    }
}

// ---------------- dual-batch cluster scan: dataflow-only sync --------------
struct __align__(16) CS {
    float tape[2][NTAPE * 33];
    float hnew[2][512];           // doubles as h_work
    float rs[2][CPB * NTAPE];
    float ws[2][CPB * NTAPE];
    float acc[2][RPC];
    float wv[2][RPC];
    float bh[RPC], gz[RPC], gr[RPC], gh[RPC], bg[RPC];
    unsigned long long mb_rs[2], mb_hn[2], mb_ws[2];
};

#define RS_BYTES (CPB * NTAPE * 4)   // 4096 (self-inclusive)
#define HN_BYTES (CPB * RPC * 4)     // 2048
#define WS_BYTES (CPB * NTAPE * 4)

__global__ __launch_bounds__(NTHREADS, 1) void scan2_kernel(
    const float* __restrict__ tape_init,
    const float* __restrict__ hwork_init,
    const float* __restrict__ W_h,
    const float* __restrict__ b_h,
    const float* __restrict__ W_write,
    const float* __restrict__ gzv,
    const float* __restrict__ grv,
    const float* __restrict__ ghv,
    const float* __restrict__ bgv,
    float* __restrict__ out)
{
    extern __shared__ char raw[];
    CS& S = *(CS*)raw;

    const int t    = threadIdx.x;
    const int lane = t & 31;
    const int cw   = t >> 5;
    const int u    = blockIdx.x >> 4;
    const int c    = blockIdx.x & 15;
    const int d0   = c * RPC;
    const float scale = 0.044194173824159216f;  // 1/sqrt(512)

    const bool isctrl = (cw == 0) || (cw == 5);
    const int  gme    = (cw == 5) ? 1 : 0;

    // ---- weights into registers ----
    unsigned long long wh[4][8], ww[4][8];
#pragma unroll
    for (int i = 0; i < 4; i++) {
        const size_t rowoff = (size_t)(d0 + cw * 4 + i) * 512;
#pragma unroll
        for (int ch = 0; ch < 4; ch++) {
            ulonglong2 a = *(const ulonglong2*)(W_h     + rowoff + ch * 128 + lane * 4);
            ulonglong2 b = *(const ulonglong2*)(W_write + rowoff + ch * 128 + lane * 4);
            wh[i][ch * 2] = a.x; wh[i][ch * 2 + 1] = a.y;
            ww[i][ch * 2] = b.x; ww[i][ch * 2 + 1] = b.y;
        }
    }

    // ---- one-time smem loads ----
#pragma unroll
    for (int g = 0; g < 2; g++) {
        int bg = 2 * u + g;
        for (int i = t; i < NTAPE * RPC; i += NTHREADS) {
            int n = i >> 5, dl = i & 31;
            S.tape[g][n * 33 + dl] = tape_init[(size_t)(bg * NTAPE + n) * DD + d0 + dl];
        }
        for (int i = t; i < 512; i += NTHREADS)
            S.hnew[g][i] = hwork_init[bg * 512 + i];
    }
    if (t < RPC) {
        S.bh[t] = b_h[d0 + t];  S.gz[t] = gzv[d0 + t];
        S.gr[t] = grv[d0 + t];  S.gh[t] = ghv[d0 + t];
        S.bg[t] = bgv[d0 + t];
    }

    const uint32_t sbase = smem_u32(&S);
    uint32_t pb[CPB];
#pragma unroll
    for (int r = 0; r < CPB; r++) pb[r] = mapa_u32(sbase, r);

    uint32_t mbrs[2], mbhn[2], mbws[2];
    uint32_t off_rs[2], off_hn[2], off_ws[2];
    uint32_t off_mbrs[2], off_mbhn[2], off_mbws[2];
#pragma unroll
    for (int g = 0; g < 2; g++) {
        mbrs[g] = smem_u32(&S.mb_rs[g]);
        mbhn[g] = smem_u32(&S.mb_hn[g]);
        mbws[g] = smem_u32(&S.mb_ws[g]);
        off_rs[g] = smem_u32(&S.rs[g][0]) - sbase;
        off_hn[g] = smem_u32(&S.hnew[g][0]) - sbase;
        off_ws[g] = smem_u32(&S.ws[g][0]) - sbase;
        off_mbrs[g] = mbrs[g] - sbase;
        off_mbhn[g] = mbhn[g] - sbase;
        off_mbws[g] = mbws[g] - sbase;
    }
    if (t == 0) {
#pragma unroll
        for (int g = 0; g < 2; g++) {
            mbar_init(mbrs[g], 1); mbar_init(mbhn[g], 1); mbar_init(mbws[g], 1);
            mbar_expect_tx(mbrs[g], RS_BYTES);
            mbar_expect_tx(mbhn[g], HN_BYTES);
            mbar_expect_tx(mbws[g], WS_BYTES);
        }
    }
    __syncthreads();

    // ---- pre-loop: acc[g] = Wh @ h_init ----
#pragma unroll
    for (int g = 0; g < 2; g++) {
        unsigned long long v[8];
#pragma unroll
        for (int ch = 0; ch < 4; ch++) {
            ulonglong2 tv = *(const ulonglong2*)(&S.hnew[g][ch * 128 + lane * 4]);
            v[ch * 2] = tv.x; v[ch * 2 + 1] = tv.y;
        }
        unsigned long long a2[4] = {0ull, 0ull, 0ull, 0ull};
#pragma unroll
        for (int i = 0; i < 4; i++)
#pragma unroll
            for (int p = 0; p < 8; p++) fma2(a2[i], wh[i][p], v[p]);
        float sa[4];
#pragma unroll
        for (int i = 0; i < 4; i++) { UF2 x; x.u = a2[i]; sa[i] = x.f.x + x.f.y; }
#pragma unroll
        for (int off = 16; off >= 1; off >>= 1) {
#pragma unroll
            for (int i = 0; i < 4; i++)
                sa[i] += __shfl_xor_sync(0xffffffffu, sa[i], off);
        }
        if (lane == 0)
            *(float4*)&S.acc[g][cw * 4] = make_float4(sa[0], sa[1], sa[2], sa[3]);
    }
    __syncthreads();
    CLUSTER_SYNC_();

    const int n4 = t >> 2, q4 = t & 3;
    // D-phase ownership: warps 0-3 -> batch 0, warps 4-7 -> batch 1; 16 rows each
    const int g2    = cw >> 2;
    const int rbase = (cw & 3) * 16;

    for (int step = 0; step < TT; step++) {
        const uint32_t par = step & 1u;

        // ---- prefetch xz (ctrl warps) ----
        float xp = 0.f, zt = 0.f;
        if (isctrl) {
            size_t row = (size_t)((2 * u + gme) * TT + step) * EE;
            xp = __ldcs(&g_xz[row + d0 + lane]);
            zt = __ldcs(&g_xz[row + 512 + d0 + lane]);
        }

        // ---- Phase A: read-score partials, push to ALL ranks (incl self) ----
#pragma unroll
        for (int g = 0; g < 2; g++) {
            float s = 0.f;
#pragma unroll
            for (int k = 0; k < 8; k++) {
                int dl = q4 * 8 + k;
                s += S.hnew[g][d0 + dl] * S.tape[g][n4 * 33 + dl];
            }
            s += __shfl_down_sync(0xffffffffu, s, 2);
            s += __shfl_down_sync(0xffffffffu, s, 1);
            if (q4 == 0) {
                uint32_t doff = off_rs[g] + (uint32_t)(c * NTAPE + n4) * 4;
#pragma unroll
                for (int r = 0; r < CPB; r++)
                    push_async(pb[r] + doff, s, pb[r] + off_mbrs[g]);
            }
        }

        // ---- Phase B (ctrl warps): wait rs, softmax, read_val, h_new ----
        if (isctrl) {
            const int g = gme;
            const int bg = 2 * u + g;
            mbar_wait_cta(mbrs[g], par);
            if (lane == 0) mbar_expect_tx(mbrs[g], RS_BYTES);
            float a0 = 0.f, a1 = 0.f, a2s = 0.f, a3s = 0.f;
#pragma unroll
            for (int cc = 0; cc < CPB; cc += 2) {
                a0  += S.rs[g][cc * NTAPE + lane];
                a1  += S.rs[g][cc * NTAPE + lane + 32];
                a2s += S.rs[g][(cc + 1) * NTAPE + lane];
                a3s += S.rs[g][(cc + 1) * NTAPE + lane + 32];
            }
            a0 = (a0 + a2s) * scale; a1 = (a1 + a3s) * scale;
            float m = fmaxf(a0, a1);
#pragma unroll
            for (int off = 16; off >= 1; off >>= 1)
                m = fmaxf(m, __shfl_xor_sync(0xffffffffu, m, off));
            float e0 = __expf(a0 - m), e1 = __expf(a1 - m);
            float ss = e0 + e1;
#pragma unroll
            for (int off = 16; off >= 1; off >>= 1)
                ss += __shfl_xor_sync(0xffffffffu, ss, off);
            float inv = 1.f / ss;
            e0 *= inv; e1 *= inv;
            float rv0 = 0.f, rv1 = 0.f, rv2 = 0.f, rv3 = 0.f;
#pragma unroll
            for (int k = 0; k < 8; k++) {
                rv0 += __shfl_sync(0xffffffffu, e0, 4 * k + 0) * S.tape[g][(4 * k + 0) * 33 + lane];
                rv1 += __shfl_sync(0xffffffffu, e0, 4 * k + 1) * S.tape[g][(4 * k + 1) * 33 + lane];
                rv2 += __shfl_sync(0xffffffffu, e0, 4 * k + 2) * S.tape[g][(4 * k + 2) * 33 + lane];
                rv3 += __shfl_sync(0xffffffffu, e0, 4 * k + 3) * S.tape[g][(4 * k + 3) * 33 + lane];
            }
#pragma unroll
            for (int k = 0; k < 8; k++) {
                rv0 += __shfl_sync(0xffffffffu, e1, 4 * k + 0) * S.tape[g][(32 + 4 * k + 0) * 33 + lane];
                rv1 += __shfl_sync(0xffffffffu, e1, 4 * k + 1) * S.tape[g][(32 + 4 * k + 1) * 33 + lane];
                rv2 += __shfl_sync(0xffffffffu, e1, 4 * k + 2) * S.tape[g][(32 + 4 * k + 2) * 33 + lane];
                rv3 += __shfl_sync(0xffffffffu, e1, 4 * k + 3) * S.tape[g][(32 + 4 * k + 3) * 33 + lane];
            }
            float rv = (rv0 + rv1) + (rv2 + rv3);
            float pre = xp + S.acc[g][lane] + rv + S.bh[lane];
            float ex2 = __expf(2.f * pre);
            float hn  = 1.f - 2.f / (ex2 + 1.f);
            // push h_new slice to ALL ranks (incl self) first — unblocks C
            uint32_t doff = off_hn[g] + (uint32_t)(d0 + lane) * 4;
#pragma unroll
            for (int r = 0; r < CPB; r++)
                push_async(pb[r] + doff, hn, pb[r] + off_mbhn[g]);
            // gate + output off the critical path
            float gi = zt * S.gz[lane] + rv * S.gr[lane] + hn * S.gh[lane] + S.bg[lane];
            gi = fminf(fmaxf(gi, -20.f), 20.f);
            float sig = 1.f / (1.f + __expf(-gi));
            out[(size_t)(bg * TT + step) * DD + d0 + lane] = hn * gi * sig;
        }

        // ---- Phase C: all warps wait h_new, dual register matvec ----
        mbar_wait_cta(mbhn[0], par);
        mbar_wait_cta(mbhn[1], par);
        if (t == 0) {
            mbar_expect_tx(mbhn[0], HN_BYTES);
            mbar_expect_tx(mbhn[1], HN_BYTES);
        }
#pragma unroll
        for (int g = 0; g < 2; g++) {
            unsigned long long v[8];
#pragma unroll
            for (int ch = 0; ch < 4; ch++) {
                ulonglong2 tv = *(const ulonglong2*)(&S.hnew[g][ch * 128 + lane * 4]);
                v[ch * 2] = tv.x; v[ch * 2 + 1] = tv.y;
            }
            unsigned long long a2[4] = {0ull, 0ull, 0ull, 0ull};
            unsigned long long b2[4] = {0ull, 0ull, 0ull, 0ull};
#pragma unroll
            for (int i = 0; i < 4; i++)
#pragma unroll
                for (int p = 0; p < 8; p++) {
                    fma2(a2[i], wh[i][p], v[p]);
                    fma2(b2[i], ww[i][p], v[p]);
                }
            float sa[4], sb[4];
#pragma unroll
            for (int i = 0; i < 4; i++) {
                UF2 x; x.u = a2[i]; sa[i] = x.f.x + x.f.y;
                UF2 y; y.u = b2[i]; sb[i] = y.f.x + y.f.y;
            }
#pragma unroll
            for (int off = 16; off >= 1; off >>= 1) {
#pragma unroll
                for (int i = 0; i < 4; i++) {
                    sa[i] += __shfl_xor_sync(0xffffffffu, sa[i], off);
                    sb[i] += __shfl_xor_sync(0xffffffffu, sb[i], off);
                }
            }
            if (lane == 0) {
                *(float4*)&S.acc[g][cw * 4] = make_float4(sa[0], sa[1], sa[2], sa[3]);
                *(float4*)&S.wv[g][cw * 4]  = make_float4(sb[0], sb[1], sb[2], sb[3]);
            }
        }
        __syncthreads();   // S3: acc/wv exchange

        // ---- write-score partials, push to ALL ranks ----
#pragma unroll
        for (int g = 0; g < 2; g++) {
            float s = 0.f;
#pragma unroll
            for (int k = 0; k < 8; k++) {
                int dl = q4 * 8 + k;
                s += S.wv[g][dl] * S.tape[g][n4 * 33 + dl];
            }
            s += __shfl_down_sync(0xffffffffu, s, 2);
            s += __shfl_down_sync(0xffffffffu, s, 1);
            if (q4 == 0) {
                uint32_t doff = off_ws[g] + (uint32_t)(c * NTAPE + n4) * 4;
#pragma unroll
                for (int r = 0; r < CPB; r++)
                    push_async(pb[r] + doff, s, pb[r] + off_mbws[g]);
            }
        }

        // ---- Phase D: per-warp wait ws + redundant softmax + tape update ----
        {
            mbar_wait_cta(mbws[g2], par);
            if (lane == 0 && (cw == 0 || cw == 4))
                mbar_expect_tx(mbws[g2], WS_BYTES);
            float a0 = 0.f, a1 = 0.f, a2s = 0.f, a3s = 0.f;
#pragma unroll
            for (int cc = 0; cc < CPB; cc += 2) {
                a0  += S.ws[g2][cc * NTAPE + lane];
                a1  += S.ws[g2][cc * NTAPE + lane + 32];
                a2s += S.ws[g2][(cc + 1) * NTAPE + lane];
                a3s += S.ws[g2][(cc + 1) * NTAPE + lane + 32];
            }
            a0 = (a0 + a2s) * scale; a1 = (a1 + a3s) * scale;
            float m = fmaxf(a0, a1);
#pragma unroll
            for (int off = 16; off >= 1; off >>= 1)
                m = fmaxf(m, __shfl_xor_sync(0xffffffffu, m, off));
            float e0 = __expf(a0 - m), e1 = __expf(a1 - m);
            float ss = e0 + e1;
#pragma unroll
            for (int off = 16; off >= 1; off >>= 1)
                ss += __shfl_xor_sync(0xffffffffu, ss, off);
            float inv = 1.f / ss;
            // attn for this warp's half: rows rbase..rbase+15
            float eh = (rbase < 32) ? e0 * inv : e1 * inv;
            float wvl = S.wv[g2][lane];
#pragma unroll
            for (int r = 0; r < 16; r++) {
                int n = rbase + r;
                float a = __shfl_sync(0xffffffffu, eh, n & 31);
                float tp = S.tape[g2][n * 33 + lane];
                S.tape[g2][n * 33 + lane] = tp - tp * a + wvl * a;
            }
        }
        __syncthreads();   // S6: tape/hnew ordering for next step
    }

    // ---- final tape output ----
#pragma unroll
    for (int g = 0; g < 2; g++) {
        int bg = 2 * u + g;
        for (int e = t; e < NTAPE * RPC; e += NTHREADS) {
            int n = e >> 5, dl = e & 31;
            out[(size_t)BB * TT * DD + (size_t)(bg * NTAPE + n) * DD + d0 + dl] =
                S.tape[g][n * 33 + dl];
        }
    }
    CLUSTER_SYNC_();
}

// ---------------- fallback scan kernel (global-memory barriers) -----------
struct ScanSmem {
    float Wh[RPC * 512];
    float Ww[RPC * 512];
    float tape[NTAPE * 33];
    float hwork[512];
    float hnew[512];
    float acc[RPC];
    float wv[RPC];
    float rv[RPC];
    float attn[NTAPE];
    float score[NTAPE];
    float bh[RPC], gz[RPC], gr[RPC], gh[RPC], bg[RPC];
};

__device__ __forceinline__ void softmax64f(const float* __restrict__ score,
                                           float* __restrict__ attn, int t)
{
    if (t < 32) {
        float a = score[t], b = score[t + 32];
        float m = fmaxf(a, b);
#pragma unroll
        for (int off = 16; off >= 1; off >>= 1)
            m = fmaxf(m, __shfl_xor_sync(0xffffffffu, m, off));
        float e0 = __expf(a - m), e1 = __expf(b - m);
        float ss = e0 + e1;
#pragma unroll
        for (int off = 16; off >= 1; off >>= 1)
            ss += __shfl_xor_sync(0xffffffffu, ss, off);
        float inv = 1.f / ss;
        attn[t] = e0 * inv;
        attn[t + 32] = e1 * inv;
    }
}

__global__ __launch_bounds__(NTHREADS, 1) void scan_kernel(
    const float* __restrict__ tape_init,
    const float* __restrict__ hwork_init,
    const float* __restrict__ W_h,
    const float* __restrict__ b_h,
    const float* __restrict__ W_write,
    const float* __restrict__ gzv,
    const float* __restrict__ grv,
    const float* __restrict__ ghv,
    const float* __restrict__ bgv,
    float* __restrict__ out)
{
    extern __shared__ char raw[];
    ScanSmem& S = *(ScanSmem*)raw;

    const int t  = threadIdx.x;
    const int b  = blockIdx.x / CPB;
    const int c  = blockIdx.x % CPB;
    const int d0 = c * RPC;
    const float scale = 0.044194173824159216f;

    for (int i = t; i < RPC * 512; i += NTHREADS) {
        S.Wh[i] = W_h[(size_t)d0 * 512 + i];
        S.Ww[i] = W_write[(size_t)d0 * 512 + i];
    }
    for (int i = t; i < NTAPE * RPC; i += NTHREADS) {
        int n = i >> 5, dl = i & 31;
        S.tape[n * 33 + dl] = tape_init[(size_t)(b * NTAPE + n) * DD + d0 + dl];
    }
    for (int i = t; i < 512; i += NTHREADS)
        S.hwork[i] = hwork_init[b * 512 + i];
    if (t < RPC) {
        S.bh[t] = b_h[d0 + t];  S.gz[t] = gzv[d0 + t];
        S.gr[t] = grv[d0 + t];  S.gh[t] = ghv[d0 + t];
        S.bg[t] = bgv[d0 + t];
    }
    __syncthreads();

    unsigned bc = 0;
    const int n4 = t >> 2, q4 = t & 3;
    const int dl8 = t >> 3, q8 = t & 7;

    for (int step = 0; step < TT; step++) {
        {
            float s = 0.f;
#pragma unroll
            for (int k = 0; k < 8; k++) {
                int dl = q4 * 8 + k;
                s += S.hwork[d0 + dl] * S.tape[n4 * 33 + dl];
            }
            s += __shfl_down_sync(0xffffffffu, s, 2);
            s += __shfl_down_sync(0xffffffffu, s, 1);
            if (q4 == 0) g_rs[(b * CPB + c) * NTAPE + n4] = s;
        }
        matvec32(S.Wh, S.hwork, S.acc);
        batch_barrier(b, (++bc) * CPB);

        if (t < NTAPE) {
            float s = 0.f;
#pragma unroll
            for (int cc = 0; cc < CPB; cc++)
                s += __ldcg(&g_rs[(b * CPB + cc) * NTAPE + t]);
            S.score[t] = s * scale;
        }
        __syncthreads();
        softmax64f(S.score, S.attn, t);
        __syncthreads();
        {
            float s = 0.f;
#pragma unroll
            for (int k = 0; k < 8; k++) {
                int n = q8 * 8 + k;
                s += S.attn[n] * S.tape[n * 33 + dl8];
            }
            s += __shfl_down_sync(0xffffffffu, s, 4);
            s += __shfl_down_sync(0xffffffffu, s, 2);
            s += __shfl_down_sync(0xffffffffu, s, 1);
            if (q8 == 0) S.rv[dl8] = s;
        }
        __syncthreads();
        if (t < RPC) {
            size_t row = (size_t)(b * TT + step) * EE;
            float xp = g_xz[row + d0 + t];
            float zt = g_xz[row + 512 + d0 + t];
            float hn = tanhf(xp + S.acc[t] + S.rv[t] + S.bh[t]);
            g_hnew[b * 512 + d0 + t] = hn;
            float gi = zt * S.gz[t] + S.rv[t] * S.gr[t] + hn * S.gh[t] + S.bg[t];
            gi = fminf(fmaxf(gi, -20.f), 20.f);
            float sig = 1.f / (1.f + __expf(-gi));
            out[(size_t)(b * TT + step) * DD + d0 + t] = hn * gi * sig;
        }
        batch_barrier(b, (++bc) * CPB);

        S.hnew[t]       = __ldcg(&g_hnew[b * 512 + t]);
        S.hnew[t + 256] = __ldcg(&g_hnew[b * 512 + t + 256]);
        __syncthreads();
        matvec32(S.Ww, S.hnew, S.wv);
        __syncthreads();
        {
            float s = 0.f;
#pragma unroll
            for (int k = 0; k < 8; k++) {
                int dl = q4 * 8 + k;
                s += S.wv[dl] * S.tape[n4 * 33 + dl];
            }
            s += __shfl_down_sync(0xffffffffu, s, 2);
            s += __shfl_down_sync(0xffffffffu, s, 1);
            if (q4 == 0) g_ws[(b * CPB + c) * NTAPE + n4] = s;
        }
        batch_barrier(b, (++bc) * CPB);

        if (t < NTAPE) {
            float s = 0.f;
#pragma unroll
            for (int cc = 0; cc < CPB; cc++)
                s += __ldcg(&g_ws[(b * CPB + cc) * NTAPE + t]);
            S.score[t] = s * scale;
        }
        __syncthreads();
        softmax64f(S.score, S.attn, t);
        __syncthreads();
        for (int e = t; e < NTAPE * RPC; e += NTHREADS) {
            int n = e >> 5, dl = e & 31;
            float a  = S.attn[n];
            float tp = S.tape[n * 33 + dl];
            S.tape[n * 33 + dl] = tp - tp * a + S.wv[dl] * a;
        }
        S.hwork[t]       = S.hnew[t];
        S.hwork[t + 256] = S.hnew[t + 256];
        __syncthreads();
    }

    for (int e = t; e < NTAPE * RPC; e += NTHREADS) {
        int n = e >> 5, dl = e & 31;
        out[(size_t)BB * TT * DD + (size_t)(b * NTAPE + n) * DD + d0 + dl] =
            S.tape[n * 33 + dl];
    }
}

// ---------------- launch ---------------------------------------------------
extern "C" void kernel_launch(void* const* d_in, const int* in_sizes, int n_in,
                              void* d_out, int out_size)
{
    const float* x         = (const float*)d_in[0];
    const float* tape_init = (const float*)d_in[1];
    const float* hwork     = (const float*)d_in[2];
    const float* W_h       = (const float*)d_in[3];
    const float* W_xz      = (const float*)d_in[4];
    const float* b_h       = (const float*)d_in[5];
    const float* W_write   = (const float*)d_in[6];
    const float* g_z       = (const float*)d_in[7];
    const float* g_r       = (const float*)d_in[8];
    const float* g_h       = (const float*)d_in[9];
    const float* b_gate    = (const float*)d_in[10];
    float* out = (float*)d_out;

    gemm_xz_kernel<<<dim3(EE / 64, (BB * TT) / 64), 256>>>(x, W_xz);

    // ---- primary: dual-batch register-weight dataflow cluster scan ----
    cudaFuncSetAttribute(scan2_kernel,
                         cudaFuncAttributeMaxDynamicSharedMemorySize,
                         (int)sizeof(CS));
    cudaError_t aerr = cudaFuncSetAttribute(
        scan2_kernel, cudaFuncAttributeNonPortableClusterSizeAllowed, 1);

    cudaLaunchConfig_t cfg = {};
    cfg.gridDim  = dim3(NCLU * CPB, 1, 1);
    cfg.blockDim = dim3(NTHREADS, 1, 1);
    cfg.dynamicSmemBytes = sizeof(CS);
    cfg.stream = 0;

    int maxClu = 0;
    cudaError_t qerr = cudaOccupancyMaxPotentialClusterSize(
        &maxClu, scan2_kernel, &cfg);

    bool launched = false;
    if (aerr == cudaSuccess && qerr == cudaSuccess && maxClu >= CPB) {
        cudaLaunchAttribute attrs[1];
        attrs[0].id = cudaLaunchAttributeClusterDimension;
        attrs[0].val.clusterDim.x = CPB;
        attrs[0].val.clusterDim.y = 1;
        attrs[0].val.clusterDim.z = 1;
        cfg.attrs = attrs;
        cfg.numAttrs = 1;
        cudaError_t lerr = cudaLaunchKernelEx(&cfg, scan2_kernel,
            tape_init, hwork, W_h, b_h, W_write, g_z, g_r, g_h, b_gate, out);
        launched = (lerr == cudaSuccess);
    }

    // ---- fallback ----
    if (!launched) {
        cudaFuncSetAttribute(scan_kernel,
                             cudaFuncAttributeMaxDynamicSharedMemorySize,
                             (int)sizeof(ScanSmem));
        init_bar_kernel<<<1, 32>>>();
        scan_kernel<<<BB * CPB, NTHREADS, sizeof(ScanSmem)>>>(
            tape_init, hwork, W_h, b_h, W_write, g_z, g_r, g_h, b_gate, out);
    }
}